// round 10
// baseline (speedup 1.0000x reference)
#include <cuda_runtime.h>
#include <cuda_fp16.h>
#include <math.h>
#include <stdint.h>

#define RR 64
#define DT_C 0.1f
#define TAU_MIN_C 0.1f
#define TAU_MAX_C 10.0f
#define SCALING_C 2.0f          // 128/64

#define MAX_M 16384
#define MAX_O 4096
#define MAX_D 4096

// scratch (device globals: no allocation allowed)
__device__ __align__(16) __half g_t_hi[MAX_M * RR];   // 2 MB
__device__ __align__(16) __half g_t_lo[MAX_M * RR];   // 2 MB
__device__ __align__(16) __half g_hB[MAX_O * RR];     // fp16 of 2*hidden
__device__ __align__(16) __half g_Ah[RR * MAX_D];     // fp16 of lora_A

// ---------------------------------------------------------------------------
// helpers
// ---------------------------------------------------------------------------
__device__ __forceinline__ uint32_t smem_u32(const void* p) {
    uint32_t a;
    asm("{ .reg .u64 t; cvta.to.shared.u64 t, %1; cvt.u32.u64 %0, t; }"
        : "=r"(a) : "l"(p));
    return a;
}
__device__ __forceinline__ uint32_t sw128(uint32_t o) { return o ^ ((o >> 3) & 0x70); }

__device__ __forceinline__ void sts128(uint32_t a, uint32_t x, uint32_t y,
                                       uint32_t z, uint32_t w) {
    asm volatile("st.shared.v4.b32 [%0], {%1,%2,%3,%4};"
                 :: "r"(a), "r"(x), "r"(y), "r"(z), "r"(w) : "memory");
}
__device__ __forceinline__ void ldm_x4(uint32_t* r, uint32_t addr) {
    asm volatile("ldmatrix.sync.aligned.m8n8.x4.shared.b16 {%0,%1,%2,%3}, [%4];"
                 : "=r"(r[0]), "=r"(r[1]), "=r"(r[2]), "=r"(r[3]) : "r"(addr));
}
// D += A * B, fp16 inputs, fp32 accum
__device__ __forceinline__ void mma16816(float* d, const uint32_t* a, const uint32_t* b) {
    asm volatile(
        "mma.sync.aligned.m16n8k16.row.col.f32.f16.f16.f32 "
        "{%0,%1,%2,%3}, {%4,%5,%6,%7}, {%8,%9}, {%0,%1,%2,%3};"
        : "+f"(d[0]), "+f"(d[1]), "+f"(d[2]), "+f"(d[3])
        : "r"(a[0]), "r"(a[1]), "r"(a[2]), "r"(a[3]), "r"(b[0]), "r"(b[1]));
}
// split pair of fp32 into hi/lo fp16x2 (packed, element order preserved)
__device__ __forceinline__ void splitH(float a, float b, uint32_t& hi, uint32_t& lo) {
    __half2 h = __floats2half2_rn(a, b);
    float2 hf = __half22float2(h);
    __half2 l = __floats2half2_rn(a - hf.x, b - hf.y);
    hi = *reinterpret_cast<uint32_t*>(&h);
    lo = *reinterpret_cast<uint32_t*>(&l);
}

// ---------------------------------------------------------------------------
// Kernel 0: convert lora_A (fp32) -> g_Ah (fp16). Tiny; runs first.
// ---------------------------------------------------------------------------
__global__ __launch_bounds__(256) void convA_kernel(const float* __restrict__ A, int n4)
{
    int i = blockIdx.x * 256 + threadIdx.x;      // index in float4 units
    if (i < n4) {
        float4 v = ((const float4*)A)[i];
        __half2 a = __floats2half2_rn(v.x, v.y);
        __half2 b = __floats2half2_rn(v.z, v.w);
        uint2 w;
        w.x = *reinterpret_cast<uint32_t*>(&a);
        w.y = *reinterpret_cast<uint32_t*>(&b);
        ((uint2*)g_Ah)[i] = w;
    }
}

// ---------------------------------------------------------------------------
// Fused kernel A:
//   blocks [0, nG1)      : GEMM1  t = x @ A^T  (fp16 2-product: (xh+xl)*Ah)
//                          2-deep register prefetch, double-buffered smem.
//   blocks [nG1, nG1+32) : liquid dynamics (overlapped; disjoint pipes)
// ---------------------------------------------------------------------------
#define G1_STAGE 24576
#define NLIQ 32

__global__ __launch_bounds__(256, 2) void fusedA(
    const float* __restrict__ x,
    const float* __restrict__ lora_B, const float* __restrict__ hidden0,
    const float* __restrict__ W_gate, const float* __restrict__ b_gate,
    const float* __restrict__ W_tau,  const float* __restrict__ b_tau,
    int M, int D, int O, int nG1)
{
    extern __shared__ char dsm[];
    uint32_t sb = (smem_u32(dsm) + 1023) & ~1023u;
    int tid = threadIdx.x, wid = tid >> 5, lane = tid & 31;

    if ((int)blockIdx.x < nG1) {
        // ================= GEMM1 path: 64(M) x 64(N), K-tiles 64 =============
        int warp_m = wid >> 1, warp_n = wid & 1;
        int tt = lane >> 3, rr = lane & 7;
        int g  = lane >> 2, tq = lane & 3;

        int m0 = blockIdx.x * 64;
        int srow = tid >> 2, scq = tid & 3;          // x: 4 thr/row, 16 floats
        const float* xg = x + (size_t)(m0 + srow) * D + scq * 16;
        const __half* ag = g_Ah + (size_t)srow * D + scq * 16;  // 16 halves=32B

        int a_row  = warp_m * 16 + (tt & 1) * 8 + rr;
        int a_colb = (tt >> 1) * 16;
        int b_row  = warp_n * 32 + (tt >> 1) * 8 + rr;
        int b_colb = (tt & 1) * 16;

        float acc[4][4];
        #pragma unroll
        for (int j = 0; j < 4; j++)
            #pragma unroll
            for (int k = 0; k < 4; k++) acc[j][k] = 0.0f;

        // 2-deep register prefetch slots
        float4 xv[2][4];
        uint4  av[2][2];
        #pragma unroll
        for (int s = 0; s < 2; s++) {
            const float4* xp = (const float4*)(xg + (size_t)s * 64);
            #pragma unroll
            for (int j = 0; j < 4; j++) xv[s][j] = xp[j];
            const uint4* ap = (const uint4*)(ag + (size_t)s * 64);
            #pragma unroll
            for (int j = 0; j < 2; j++) av[s][j] = ap[j];
        }

        uint32_t xbase = (uint32_t)(srow * 128 + scq * 32);
        uint32_t abase = (uint32_t)(srow * 128 + scq * 32);

        int nkt = D >> 6;
        for (int kt = 0; kt < nkt; kt++) {
            int s = kt & 1;
            uint32_t st = sb + s * G1_STAGE;
            uint32_t xhi = st, xlo = st + 8192, ahh = st + 16384;

            // STS stage kt (regs loaded 2 iterations ago)
            #pragma unroll
            for (int j = 0; j < 2; j++) {
                uint32_t h0, l0, h1, l1, h2, l2, h3, l3;
                splitH(xv[s][2*j].x,   xv[s][2*j].y,   h0, l0);
                splitH(xv[s][2*j].z,   xv[s][2*j].w,   h1, l1);
                splitH(xv[s][2*j+1].x, xv[s][2*j+1].y, h2, l2);
                splitH(xv[s][2*j+1].z, xv[s][2*j+1].w, h3, l3);
                uint32_t off = sw128(xbase + j * 16);
                sts128(xhi + off, h0, h1, h2, h3);
                sts128(xlo + off, l0, l1, l2, l3);
                uint32_t aoff = sw128(abase + j * 16);
                sts128(ahh + aoff, av[s][j].x, av[s][j].y, av[s][j].z, av[s][j].w);
            }
            __syncthreads();

            if (kt + 2 < nkt) {       // refill slot s for tile kt+2
                const float4* xp = (const float4*)(xg + (size_t)(kt + 2) * 64);
                #pragma unroll
                for (int j = 0; j < 4; j++) xv[s][j] = xp[j];
                const uint4* ap = (const uint4*)(ag + (size_t)(kt + 2) * 64);
                #pragma unroll
                for (int j = 0; j < 2; j++) av[s][j] = ap[j];
            }

            #pragma unroll
            for (int kk = 0; kk < 4; kk++) {
                uint32_t bh[4][2];
                #pragma unroll
                for (int np = 0; np < 2; np++) {
                    uint32_t off = sw128((uint32_t)((b_row + np * 16) * 128 + b_colb + kk * 32));
                    uint32_t r4[4];
                    ldm_x4(r4, ahh + off);
                    bh[2*np][0] = r4[0]; bh[2*np][1] = r4[1];
                    bh[2*np+1][0] = r4[2]; bh[2*np+1][1] = r4[3];
                }
                uint32_t axh[4], axl[4];
                uint32_t off = sw128((uint32_t)(a_row * 128 + a_colb + kk * 32));
                ldm_x4(axh, xhi + off);
                ldm_x4(axl, xlo + off);
                #pragma unroll
                for (int nt = 0; nt < 4; nt++) {
                    mma16816(acc[nt], axh, bh[nt]);
                    mma16816(acc[nt], axl, bh[nt]);
                }
            }
        }

        int m = m0 + warp_m * 16 + g;
        #pragma unroll
        for (int nt = 0; nt < 4; nt++) {
            int n = warp_n * 32 + nt * 8 + 2 * tq;
            uint32_t hi, lo;
            splitH(acc[nt][0], acc[nt][1], hi, lo);
            *(uint32_t*)(g_t_hi + (size_t)m * RR + n) = hi;
            *(uint32_t*)(g_t_lo + (size_t)m * RR + n) = lo;
            splitH(acc[nt][2], acc[nt][3], hi, lo);
            *(uint32_t*)(g_t_hi + (size_t)(m + 8) * RR + n) = hi;
            *(uint32_t*)(g_t_lo + (size_t)(m + 8) * RR + n) = lo;
        }
    } else {
        // ================= liquid path (shfl form, h-half weights in smem) ===
        float* WT2 = (float*)(dsm + 1024);   // [64][132]
        for (int idx = tid; idx < 128 * 64; idx += 256) {
            int r = idx >> 6, k2 = idx & 63;
            if (r < 64) WT2[k2 * 132 + r]             = W_gate[r * 128 + 64 + k2];
            else        WT2[k2 * 132 + 64 + (r - 64)] = W_tau[(r - 64) * 128 + 64 + k2];
        }
        __syncthreads();

        int lb = blockIdx.x - nG1;
        int gw = lb * 8 + wid;
        int rows_per_warp = O / (NLIQ * 8);          // 16
        int base = gw * rows_per_warp;

        float bg0 = b_gate[lane], bg1 = b_gate[lane + 32];
        float bt0 = b_tau[lane],  bt1 = b_tau[lane + 32];

        for (int p = 0; p < rows_per_warp / 4; p++) {
            int o4 = base + p * 4;
            float tg0[4], tg1[4], h0[4], h1[4];
            #pragma unroll
            for (int j = 0; j < 4; j++) {
                tg0[j] = lora_B[(size_t)(o4 + j) * RR + lane];
                tg1[j] = lora_B[(size_t)(o4 + j) * RR + lane + 32];
                h0[j]  = hidden0[(size_t)(o4 + j) * RR + lane];
                h1[j]  = hidden0[(size_t)(o4 + j) * RR + lane + 32];
            }

            float pg0[4], pg1[4], pt0[4], pt1[4];
            #pragma unroll
            for (int j = 0; j < 4; j++) { pg0[j] = bg0; pg1[j] = bg1; pt0[j] = bt0; pt1[j] = bt1; }
            #pragma unroll 2
            for (int k0 = 0; k0 < 32; k0 += 4) {
                float4 wg0A = *(const float4*)(W_gate + lane * 128 + k0);
                float4 wg1A = *(const float4*)(W_gate + (lane + 32) * 128 + k0);
                float4 wt0A = *(const float4*)(W_tau  + lane * 128 + k0);
                float4 wt1A = *(const float4*)(W_tau  + (lane + 32) * 128 + k0);
                float4 wg0B = *(const float4*)(W_gate + lane * 128 + 32 + k0);
                float4 wg1B = *(const float4*)(W_gate + (lane + 32) * 128 + 32 + k0);
                float4 wt0B = *(const float4*)(W_tau  + lane * 128 + 32 + k0);
                float4 wt1B = *(const float4*)(W_tau  + (lane + 32) * 128 + 32 + k0);
                #pragma unroll
                for (int e = 0; e < 4; e++) {
                    float g0 = ((const float*)&wg0A)[e], g1 = ((const float*)&wg1A)[e];
                    float t0 = ((const float*)&wt0A)[e], t1 = ((const float*)&wt1A)[e];
                    float g0b = ((const float*)&wg0B)[e], g1b = ((const float*)&wg1B)[e];
                    float t0b = ((const float*)&wt0B)[e], t1b = ((const float*)&wt1B)[e];
                    #pragma unroll
                    for (int j = 0; j < 4; j++) {
                        float v  = __shfl_sync(0xffffffffu, tg0[j], k0 + e);
                        float v2 = __shfl_sync(0xffffffffu, tg1[j], k0 + e);
                        pg0[j] += v * g0;   pg1[j] += v * g1;
                        pt0[j] += v * t0;   pt1[j] += v * t1;
                        pg0[j] += v2 * g0b; pg1[j] += v2 * g1b;
                        pt0[j] += v2 * t0b; pt1[j] += v2 * t1b;
                    }
                }
            }

            #pragma unroll
            for (int step = 0; step < 3; step++) {
                float ga0[4], ga1[4], ta0[4], ta1[4];
                #pragma unroll
                for (int j = 0; j < 4; j++) { ga0[j] = pg0[j]; ga1[j] = pg1[j]; ta0[j] = pt0[j]; ta1[j] = pt1[j]; }
                #pragma unroll 8
                for (int k = 0; k < 32; k++) {
                    float wg0 = WT2[k * 132 + lane],      wg1 = WT2[k * 132 + lane + 32];
                    float wt0 = WT2[k * 132 + 64 + lane], wt1 = WT2[k * 132 + 96 + lane];
                    float wg0b = WT2[(32 + k) * 132 + lane],      wg1b = WT2[(32 + k) * 132 + lane + 32];
                    float wt0b = WT2[(32 + k) * 132 + 64 + lane], wt1b = WT2[(32 + k) * 132 + 96 + lane];
                    #pragma unroll
                    for (int j = 0; j < 4; j++) {
                        float v  = __shfl_sync(0xffffffffu, h0[j], k);
                        float v2 = __shfl_sync(0xffffffffu, h1[j], k);
                        ga0[j] += v * wg0;  ga1[j] += v * wg1;
                        ta0[j] += v * wt0;  ta1[j] += v * wt1;
                        ga0[j] += v2 * wg0b; ga1[j] += v2 * wg1b;
                        ta0[j] += v2 * wt0b; ta1[j] += v2 * wt1b;
                    }
                }
                #pragma unroll
                for (int j = 0; j < 4; j++) {
                    float f0   = 1.0f / (1.0f + expf(-ga0[j]));
                    float f1   = 1.0f / (1.0f + expf(-ga1[j]));
                    float tau0 = TAU_MIN_C + (TAU_MAX_C - TAU_MIN_C) / (1.0f + expf(-ta0[j]));
                    float tau1 = TAU_MIN_C + (TAU_MAX_C - TAU_MIN_C) / (1.0f + expf(-ta1[j]));
                    float a0   = 1.0f / tau0 + f0;
                    float a1   = 1.0f / tau1 + f1;
                    float d0   = expf(-a0 * DT_C);
                    float d1   = expf(-a1 * DT_C);
                    h0[j] = h0[j] * d0 + (f0 / a0) * tg0[j] * (1.0f - d0);
                    h1[j] = h1[j] * d1 + (f1 / a1) * tg1[j] * (1.0f - d1);
                }
            }

            #pragma unroll
            for (int j = 0; j < 4; j++) {
                g_hB[(size_t)(o4 + j) * RR + lane]      = __float2half_rn(SCALING_C * h0[j]);
                g_hB[(size_t)(o4 + j) * RR + lane + 32] = __float2half_rn(SCALING_C * h1[j]);
            }
        }
    }
}

// ---------------------------------------------------------------------------
// Kernel B: out = (th+tl) @ Bh^T, K = 64 single shot.
// CTA: 128(M) x 512(O) via o-loop of 4 x 128-tiles; t loaded to smem ONCE,
// B double-buffered (LDG prefetch into regs during compute). 2 CTAs/SM.
// ---------------------------------------------------------------------------
__global__ __launch_bounds__(256, 2) void gemm2_mma(
    float* __restrict__ out, int M, int O)
{
    extern __shared__ char dsm[];
    uint32_t sb  = (smem_u32(dsm) + 1023) & ~1023u;
    uint32_t thi = sb;                 // 16 KB
    uint32_t tlo = sb + 16384;         // 16 KB
    uint32_t bst = sb + 32768;         // 2 x 16 KB B stages

    int tid = threadIdx.x, wid = tid >> 5, lane = tid & 31;
    int warp_m = wid & 1, warp_n = wid >> 1;
    int tt = lane >> 3, rr = lane & 7;
    int g  = lane >> 2, tq = lane & 3;

    int m0   = blockIdx.x * 128;
    int obase = blockIdx.y * 512;

    // t tiles into smem (once)
    #pragma unroll
    for (int j = 0; j < 4; j++) {
        int i = tid + 256 * j;
        int row = i >> 3, c = i & 7;
        uint4 vh = ((const uint4*)(g_t_hi + (size_t)(m0 + row) * RR))[c];
        uint4 vl = ((const uint4*)(g_t_lo + (size_t)(m0 + row) * RR))[c];
        uint32_t off = sw128((uint32_t)(row * 128 + c * 16));
        sts128(thi + off, vh.x, vh.y, vh.z, vh.w);
        sts128(tlo + off, vl.x, vl.y, vl.z, vl.w);
    }

    // prefetch B tile 0 into regs
    uint4 bv[4];
    #pragma unroll
    for (int j = 0; j < 4; j++) {
        int i = tid + 256 * j;
        int row = i >> 3, c = i & 7;
        bv[j] = ((const uint4*)(g_hB + (size_t)(obase + row) * RR))[c];
    }

    int a_row  = warp_m * 64 + (tt & 1) * 8 + rr;
    int a_colb = (tt >> 1) * 16;
    int b_row  = warp_n * 32 + (tt >> 1) * 8 + rr;
    int b_colb = (tt & 1) * 16;

    #pragma unroll 1
    for (int ot = 0; ot < 4; ot++) {
        int s = ot & 1;
        uint32_t bh_s = bst + s * 16384;
        int o0 = obase + ot * 128;

        // STS B(ot) from regs into stage s
        #pragma unroll
        for (int j = 0; j < 4; j++) {
            int i = tid + 256 * j;
            int row = i >> 3, c = i & 7;
            sts128(bh_s + sw128((uint32_t)(row * 128 + c * 16)),
                   bv[j].x, bv[j].y, bv[j].z, bv[j].w);
        }
        __syncthreads();

        // prefetch B(ot+1) into regs (overlaps compute)
        if (ot < 3) {
            #pragma unroll
            for (int j = 0; j < 4; j++) {
                int i = tid + 256 * j;
                int row = i >> 3, c = i & 7;
                bv[j] = ((const uint4*)(g_hB + (size_t)(obase + (ot + 1) * 128 + row) * RR))[c];
            }
        }

        float acc[4][4][4];
        #pragma unroll
        for (int i = 0; i < 4; i++)
            #pragma unroll
            for (int j = 0; j < 4; j++)
                #pragma unroll
                for (int k = 0; k < 4; k++) acc[i][j][k] = 0.0f;

        #pragma unroll
        for (int kk = 0; kk < 4; kk++) {
            uint32_t bh[4][2];
            #pragma unroll
            for (int np = 0; np < 2; np++) {
                uint32_t off = sw128((uint32_t)((b_row + np * 16) * 128 + b_colb + kk * 32));
                uint32_t r4[4];
                ldm_x4(r4, bh_s + off);
                bh[2*np][0] = r4[0]; bh[2*np][1] = r4[1];
                bh[2*np+1][0] = r4[2]; bh[2*np+1][1] = r4[3];
            }
            #pragma unroll
            for (int mt = 0; mt < 4; mt++) {
                uint32_t ath[4], atl[4];
                uint32_t off = sw128((uint32_t)((a_row + mt * 16) * 128 + a_colb + kk * 32));
                ldm_x4(ath, thi + off);
                ldm_x4(atl, tlo + off);
                #pragma unroll
                for (int nt = 0; nt < 4; nt++) {
                    mma16816(acc[mt][nt], ath, bh[nt]);
                    mma16816(acc[mt][nt], atl, bh[nt]);
                }
            }
        }

        #pragma unroll
        for (int mt = 0; mt < 4; mt++) {
            int m = m0 + warp_m * 64 + mt * 16 + g;
            #pragma unroll
            for (int nt = 0; nt < 4; nt++) {
                int o = o0 + warp_n * 32 + nt * 8 + 2 * tq;
                *(float2*)(out + (size_t)m * O + o)       = make_float2(acc[mt][nt][0], acc[mt][nt][1]);
                *(float2*)(out + (size_t)(m + 8) * O + o) = make_float2(acc[mt][nt][2], acc[mt][nt][3]);
            }
        }
    }
}

// ---------------------------------------------------------------------------
extern "C" void kernel_launch(void* const* d_in, const int* in_sizes, int n_in,
                              void* d_out, int out_size)
{
    const float* x       = (const float*)d_in[0];
    const float* lora_A  = (const float*)d_in[1];
    const float* lora_B  = (const float*)d_in[2];
    const float* hidden0 = (const float*)d_in[3];
    const float* W_gate  = (const float*)d_in[4];
    const float* b_gate  = (const float*)d_in[5];
    const float* W_tau   = (const float*)d_in[6];
    const float* b_tau   = (const float*)d_in[7];
    float* out = (float*)d_out;

    int R = in_sizes[5];                 // 64
    int D = in_sizes[1] / R;             // 4096
    int O = in_sizes[2] / R;             // 4096
    int M = in_sizes[0] / D;             // 16384

    const int smemA = 2 * G1_STAGE + 1024;     // 50176
    const int smemB = 4 * 16384 + 1024;        // 66560

    cudaFuncSetAttribute(fusedA,
                         cudaFuncAttributeMaxDynamicSharedMemorySize, smemA);
    cudaFuncSetAttribute(gemm2_mma,
                         cudaFuncAttributeMaxDynamicSharedMemorySize, smemB);

    int nA4 = (R * D) / 4;
    convA_kernel<<<(nA4 + 255) / 256, 256>>>(lora_A, nA4);

    int nG1 = M / 64;                    // 256
    fusedA<<<nG1 + NLIQ, 256, smemA>>>(x, lora_B, hidden0,
                                       W_gate, b_gate, W_tau, b_tau,
                                       M, D, O, nG1);

    dim3 g2(M / 128, O / 512);
    gemm2_mma<<<g2, 256, smemB>>>(out, M, O);
}

// round 11
// speedup vs baseline: 1.1742x; 1.1742x over previous
#include <cuda_runtime.h>
#include <cuda_fp16.h>
#include <math.h>
#include <stdint.h>

#define RR 64
#define DT_C 0.1f
#define TAU_MIN_C 0.1f
#define TAU_MAX_C 10.0f
#define SCALING_C 2.0f          // 128/64

#define MAX_M 16384
#define MAX_O 4096
#define MAX_D 4096

// scratch (device globals: no allocation allowed)
__device__ __align__(16) __half g_t[MAX_M * RR];      // 2 MB fp16 t
__device__ __align__(16) __half g_hB[MAX_O * RR];     // fp16 of 2*hidden
__device__ __align__(16) __half g_Ah[RR * MAX_D];     // fp16 of lora_A

// ---------------------------------------------------------------------------
// helpers
// ---------------------------------------------------------------------------
__device__ __forceinline__ uint32_t smem_u32(const void* p) {
    uint32_t a;
    asm("{ .reg .u64 t; cvta.to.shared.u64 t, %1; cvt.u32.u64 %0, t; }"
        : "=r"(a) : "l"(p));
    return a;
}
__device__ __forceinline__ uint32_t sw128(uint32_t o) { return o ^ ((o >> 3) & 0x70); }

__device__ __forceinline__ void sts128(uint32_t a, uint32_t x, uint32_t y,
                                       uint32_t z, uint32_t w) {
    asm volatile("st.shared.v4.b32 [%0], {%1,%2,%3,%4};"
                 :: "r"(a), "r"(x), "r"(y), "r"(z), "r"(w) : "memory");
}
__device__ __forceinline__ void ldm_x4(uint32_t* r, uint32_t addr) {
    asm volatile("ldmatrix.sync.aligned.m8n8.x4.shared.b16 {%0,%1,%2,%3}, [%4];"
                 : "=r"(r[0]), "=r"(r[1]), "=r"(r[2]), "=r"(r[3]) : "r"(addr));
}
// D += A * B, fp16 inputs, fp32 accum
__device__ __forceinline__ void mma16816(float* d, const uint32_t* a, const uint32_t* b) {
    asm volatile(
        "mma.sync.aligned.m16n8k16.row.col.f32.f16.f16.f32 "
        "{%0,%1,%2,%3}, {%4,%5,%6,%7}, {%8,%9}, {%0,%1,%2,%3};"
        : "+f"(d[0]), "+f"(d[1]), "+f"(d[2]), "+f"(d[3])
        : "r"(a[0]), "r"(a[1]), "r"(a[2]), "r"(a[3]), "r"(b[0]), "r"(b[1]));
}
__device__ __forceinline__ uint32_t packH(float a, float b) {
    __half2 h = __floats2half2_rn(a, b);
    return *reinterpret_cast<uint32_t*>(&h);
}

// ---------------------------------------------------------------------------
// Kernel 0: convert lora_A (fp32) -> g_Ah (fp16). Tiny; runs first.
// ---------------------------------------------------------------------------
__global__ __launch_bounds__(256) void convA_kernel(const float* __restrict__ A, int n4)
{
    int i = blockIdx.x * 256 + threadIdx.x;      // index in float4 units
    if (i < n4) {
        float4 v = ((const float4*)A)[i];
        uint2 w;
        w.x = packH(v.x, v.y);
        w.y = packH(v.z, v.w);
        ((uint2*)g_Ah)[i] = w;
    }
}

// ---------------------------------------------------------------------------
// Fused kernel A:
//   blocks [0, nG1)      : GEMM1  t = x @ A^T  (single-product fp16)
//   blocks [nG1, nG1+32) : liquid dynamics (overlapped; disjoint pipes)
// 3 CTAs/SM (288 blocks in one wave) for latency hiding.
// ---------------------------------------------------------------------------
#define G1_STAGE 16384
#define NLIQ 32

__global__ __launch_bounds__(256, 3) void fusedA(
    const float* __restrict__ x,
    const float* __restrict__ lora_B, const float* __restrict__ hidden0,
    const float* __restrict__ W_gate, const float* __restrict__ b_gate,
    const float* __restrict__ W_tau,  const float* __restrict__ b_tau,
    int M, int D, int O, int nG1)
{
    extern __shared__ char dsm[];
    uint32_t sb = (smem_u32(dsm) + 1023) & ~1023u;
    int tid = threadIdx.x, wid = tid >> 5, lane = tid & 31;

    if ((int)blockIdx.x < nG1) {
        // ================= GEMM1 path: 64(M) x 64(N), K-tiles 64 =============
        int warp_m = wid >> 1, warp_n = wid & 1;
        int tt = lane >> 3, rr = lane & 7;
        int g  = lane >> 2, tq = lane & 3;

        int m0 = blockIdx.x * 64;
        int srow = tid >> 2, scq = tid & 3;          // 4 thr/row, 16 elements
        const float* xg = x + (size_t)(m0 + srow) * D + scq * 16;
        const __half* ag = g_Ah + (size_t)srow * D + scq * 16;

        int a_row  = warp_m * 16 + (tt & 1) * 8 + rr;
        int a_colb = (tt >> 1) * 16;
        int b_row  = warp_n * 32 + (tt >> 1) * 8 + rr;
        int b_colb = (tt & 1) * 16;

        float acc[4][4];
        #pragma unroll
        for (int j = 0; j < 4; j++)
            #pragma unroll
            for (int k = 0; k < 4; k++) acc[j][k] = 0.0f;

        float4 xv[4];
        uint4  av[2];
        #pragma unroll
        for (int j = 0; j < 4; j++) xv[j] = ((const float4*)xg)[j];
        #pragma unroll
        for (int j = 0; j < 2; j++) av[j] = ((const uint4*)ag)[j];

        uint32_t base = (uint32_t)(srow * 128 + scq * 32);

        int nkt = D >> 6;
        for (int kt = 0; kt < nkt; kt++) {
            uint32_t st = sb + (kt & 1) * G1_STAGE;
            uint32_t xh = st, ah = st + 8192;

            // STS stage kt (regs hold tile kt)
            #pragma unroll
            for (int j = 0; j < 2; j++) {
                uint32_t h0 = packH(xv[2*j].x,   xv[2*j].y);
                uint32_t h1 = packH(xv[2*j].z,   xv[2*j].w);
                uint32_t h2 = packH(xv[2*j+1].x, xv[2*j+1].y);
                uint32_t h3 = packH(xv[2*j+1].z, xv[2*j+1].w);
                uint32_t off = sw128(base + j * 16);
                sts128(xh + off, h0, h1, h2, h3);
                sts128(ah + off, av[j].x, av[j].y, av[j].z, av[j].w);
            }
            __syncthreads();

            if (kt + 1 < nkt) {
                const float4* xp = (const float4*)(xg + (size_t)(kt + 1) * 64);
                #pragma unroll
                for (int j = 0; j < 4; j++) xv[j] = xp[j];
                const uint4* ap = (const uint4*)(ag + (size_t)(kt + 1) * 64);
                #pragma unroll
                for (int j = 0; j < 2; j++) av[j] = ap[j];
            }

            #pragma unroll
            for (int kk = 0; kk < 4; kk++) {
                uint32_t bh[4][2];
                #pragma unroll
                for (int np = 0; np < 2; np++) {
                    uint32_t off = sw128((uint32_t)((b_row + np * 16) * 128 + b_colb + kk * 32));
                    uint32_t r4[4];
                    ldm_x4(r4, ah + off);
                    bh[2*np][0] = r4[0]; bh[2*np][1] = r4[1];
                    bh[2*np+1][0] = r4[2]; bh[2*np+1][1] = r4[3];
                }
                uint32_t ax[4];
                uint32_t off = sw128((uint32_t)(a_row * 128 + a_colb + kk * 32));
                ldm_x4(ax, xh + off);
                #pragma unroll
                for (int nt = 0; nt < 4; nt++)
                    mma16816(acc[nt], ax, bh[nt]);
            }
        }

        int m = m0 + warp_m * 16 + g;
        #pragma unroll
        for (int nt = 0; nt < 4; nt++) {
            int n = warp_n * 32 + nt * 8 + 2 * tq;
            *(uint32_t*)(g_t + (size_t)m * RR + n)       = packH(acc[nt][0], acc[nt][1]);
            *(uint32_t*)(g_t + (size_t)(m + 8) * RR + n) = packH(acc[nt][2], acc[nt][3]);
        }
    } else {
        // ================= liquid path (shfl form, h-half weights in smem) ===
        float* WT2 = (float*)(dsm + 1024);   // [64][132]
        for (int idx = tid; idx < 128 * 64; idx += 256) {
            int r = idx >> 6, k2 = idx & 63;
            if (r < 64) WT2[k2 * 132 + r]             = W_gate[r * 128 + 64 + k2];
            else        WT2[k2 * 132 + 64 + (r - 64)] = W_tau[(r - 64) * 128 + 64 + k2];
        }
        __syncthreads();

        int lb = blockIdx.x - nG1;
        int gw = lb * 8 + wid;
        int rows_per_warp = O / (NLIQ * 8);          // 16
        int base = gw * rows_per_warp;

        float bg0 = b_gate[lane], bg1 = b_gate[lane + 32];
        float bt0 = b_tau[lane],  bt1 = b_tau[lane + 32];

        for (int p = 0; p < rows_per_warp / 4; p++) {
            int o4 = base + p * 4;
            float tg0[4], tg1[4], h0[4], h1[4];
            #pragma unroll
            for (int j = 0; j < 4; j++) {
                tg0[j] = lora_B[(size_t)(o4 + j) * RR + lane];
                tg1[j] = lora_B[(size_t)(o4 + j) * RR + lane + 32];
                h0[j]  = hidden0[(size_t)(o4 + j) * RR + lane];
                h1[j]  = hidden0[(size_t)(o4 + j) * RR + lane + 32];
            }

            float pg0[4], pg1[4], pt0[4], pt1[4];
            #pragma unroll
            for (int j = 0; j < 4; j++) { pg0[j] = bg0; pg1[j] = bg1; pt0[j] = bt0; pt1[j] = bt1; }
            #pragma unroll 2
            for (int k0 = 0; k0 < 32; k0 += 4) {
                float4 wg0A = *(const float4*)(W_gate + lane * 128 + k0);
                float4 wg1A = *(const float4*)(W_gate + (lane + 32) * 128 + k0);
                float4 wt0A = *(const float4*)(W_tau  + lane * 128 + k0);
                float4 wt1A = *(const float4*)(W_tau  + (lane + 32) * 128 + k0);
                float4 wg0B = *(const float4*)(W_gate + lane * 128 + 32 + k0);
                float4 wg1B = *(const float4*)(W_gate + (lane + 32) * 128 + 32 + k0);
                float4 wt0B = *(const float4*)(W_tau  + lane * 128 + 32 + k0);
                float4 wt1B = *(const float4*)(W_tau  + (lane + 32) * 128 + 32 + k0);
                #pragma unroll
                for (int e = 0; e < 4; e++) {
                    float g0 = ((const float*)&wg0A)[e], g1 = ((const float*)&wg1A)[e];
                    float t0 = ((const float*)&wt0A)[e], t1 = ((const float*)&wt1A)[e];
                    float g0b = ((const float*)&wg0B)[e], g1b = ((const float*)&wg1B)[e];
                    float t0b = ((const float*)&wt0B)[e], t1b = ((const float*)&wt1B)[e];
                    #pragma unroll
                    for (int j = 0; j < 4; j++) {
                        float v  = __shfl_sync(0xffffffffu, tg0[j], k0 + e);
                        float v2 = __shfl_sync(0xffffffffu, tg1[j], k0 + e);
                        pg0[j] += v * g0;   pg1[j] += v * g1;
                        pt0[j] += v * t0;   pt1[j] += v * t1;
                        pg0[j] += v2 * g0b; pg1[j] += v2 * g1b;
                        pt0[j] += v2 * t0b; pt1[j] += v2 * t1b;
                    }
                }
            }

            #pragma unroll
            for (int step = 0; step < 3; step++) {
                float ga0[4], ga1[4], ta0[4], ta1[4];
                #pragma unroll
                for (int j = 0; j < 4; j++) { ga0[j] = pg0[j]; ga1[j] = pg1[j]; ta0[j] = pt0[j]; ta1[j] = pt1[j]; }
                #pragma unroll 8
                for (int k = 0; k < 32; k++) {
                    float wg0 = WT2[k * 132 + lane],      wg1 = WT2[k * 132 + lane + 32];
                    float wt0 = WT2[k * 132 + 64 + lane], wt1 = WT2[k * 132 + 96 + lane];
                    float wg0b = WT2[(32 + k) * 132 + lane],      wg1b = WT2[(32 + k) * 132 + lane + 32];
                    float wt0b = WT2[(32 + k) * 132 + 64 + lane], wt1b = WT2[(32 + k) * 132 + 96 + lane];
                    #pragma unroll
                    for (int j = 0; j < 4; j++) {
                        float v  = __shfl_sync(0xffffffffu, h0[j], k);
                        float v2 = __shfl_sync(0xffffffffu, h1[j], k);
                        ga0[j] += v * wg0;  ga1[j] += v * wg1;
                        ta0[j] += v * wt0;  ta1[j] += v * wt1;
                        ga0[j] += v2 * wg0b; ga1[j] += v2 * wg1b;
                        ta0[j] += v2 * wt0b; ta1[j] += v2 * wt1b;
                    }
                }
                #pragma unroll
                for (int j = 0; j < 4; j++) {
                    float f0   = 1.0f / (1.0f + expf(-ga0[j]));
                    float f1   = 1.0f / (1.0f + expf(-ga1[j]));
                    float tau0 = TAU_MIN_C + (TAU_MAX_C - TAU_MIN_C) / (1.0f + expf(-ta0[j]));
                    float tau1 = TAU_MIN_C + (TAU_MAX_C - TAU_MIN_C) / (1.0f + expf(-ta1[j]));
                    float a0   = 1.0f / tau0 + f0;
                    float a1   = 1.0f / tau1 + f1;
                    float d0   = expf(-a0 * DT_C);
                    float d1   = expf(-a1 * DT_C);
                    h0[j] = h0[j] * d0 + (f0 / a0) * tg0[j] * (1.0f - d0);
                    h1[j] = h1[j] * d1 + (f1 / a1) * tg1[j] * (1.0f - d1);
                }
            }

            #pragma unroll
            for (int j = 0; j < 4; j++) {
                g_hB[(size_t)(o4 + j) * RR + lane]      = __float2half_rn(SCALING_C * h0[j]);
                g_hB[(size_t)(o4 + j) * RR + lane + 32] = __float2half_rn(SCALING_C * h1[j]);
            }
        }
    }
}

// ---------------------------------------------------------------------------
// Kernel B: out = t @ Bh^T (single-product fp16), K = 64 single shot.
// CTA: 128(M) x 512(O) via o-loop of 4 x 128-tiles; t in smem once,
// B double-buffered via register prefetch. 2 CTAs/SM.
// ---------------------------------------------------------------------------
__global__ __launch_bounds__(256, 2) void gemm2_mma(
    float* __restrict__ out, int M, int O)
{
    extern __shared__ char dsm[];
    uint32_t sb  = (smem_u32(dsm) + 1023) & ~1023u;
    uint32_t thi = sb;                 // 16 KB
    uint32_t bst = sb + 16384;         // 2 x 16 KB B stages

    int tid = threadIdx.x, wid = tid >> 5, lane = tid & 31;
    int warp_m = wid & 1, warp_n = wid >> 1;
    int tt = lane >> 3, rr = lane & 7;
    int g  = lane >> 2, tq = lane & 3;

    int m0    = blockIdx.x * 128;
    int obase = blockIdx.y * 512;

    // t tile into smem (once)
    #pragma unroll
    for (int j = 0; j < 4; j++) {
        int i = tid + 256 * j;
        int row = i >> 3, c = i & 7;
        uint4 vh = ((const uint4*)(g_t + (size_t)(m0 + row) * RR))[c];
        sts128(thi + sw128((uint32_t)(row * 128 + c * 16)),
               vh.x, vh.y, vh.z, vh.w);
    }

    // prefetch B tile 0 into regs
    uint4 bv[4];
    #pragma unroll
    for (int j = 0; j < 4; j++) {
        int i = tid + 256 * j;
        int row = i >> 3, c = i & 7;
        bv[j] = ((const uint4*)(g_hB + (size_t)(obase + row) * RR))[c];
    }

    int a_row  = warp_m * 64 + (tt & 1) * 8 + rr;
    int a_colb = (tt >> 1) * 16;
    int b_row  = warp_n * 32 + (tt >> 1) * 8 + rr;
    int b_colb = (tt & 1) * 16;

    #pragma unroll 1
    for (int ot = 0; ot < 4; ot++) {
        int s = ot & 1;
        uint32_t bh_s = bst + s * 16384;
        int o0 = obase + ot * 128;

        #pragma unroll
        for (int j = 0; j < 4; j++) {
            int i = tid + 256 * j;
            int row = i >> 3, c = i & 7;
            sts128(bh_s + sw128((uint32_t)(row * 128 + c * 16)),
                   bv[j].x, bv[j].y, bv[j].z, bv[j].w);
        }
        __syncthreads();

        if (ot < 3) {
            #pragma unroll
            for (int j = 0; j < 4; j++) {
                int i = tid + 256 * j;
                int row = i >> 3, c = i & 7;
                bv[j] = ((const uint4*)(g_hB + (size_t)(obase + (ot + 1) * 128 + row) * RR))[c];
            }
        }

        float acc[4][4][4];
        #pragma unroll
        for (int i = 0; i < 4; i++)
            #pragma unroll
            for (int j = 0; j < 4; j++)
                #pragma unroll
                for (int k = 0; k < 4; k++) acc[i][j][k] = 0.0f;

        #pragma unroll
        for (int kk = 0; kk < 4; kk++) {
            uint32_t bh[4][2];
            #pragma unroll
            for (int np = 0; np < 2; np++) {
                uint32_t off = sw128((uint32_t)((b_row + np * 16) * 128 + b_colb + kk * 32));
                uint32_t r4[4];
                ldm_x4(r4, bh_s + off);
                bh[2*np][0] = r4[0]; bh[2*np][1] = r4[1];
                bh[2*np+1][0] = r4[2]; bh[2*np+1][1] = r4[3];
            }
            #pragma unroll
            for (int mt = 0; mt < 4; mt++) {
                uint32_t ath[4];
                uint32_t off = sw128((uint32_t)((a_row + mt * 16) * 128 + a_colb + kk * 32));
                ldm_x4(ath, thi + off);
                #pragma unroll
                for (int nt = 0; nt < 4; nt++)
                    mma16816(acc[mt][nt], ath, bh[nt]);
            }
        }

        #pragma unroll
        for (int mt = 0; mt < 4; mt++) {
            int m = m0 + warp_m * 64 + mt * 16 + g;
            #pragma unroll
            for (int nt = 0; nt < 4; nt++) {
                int o = o0 + warp_n * 32 + nt * 8 + 2 * tq;
                *(float2*)(out + (size_t)m * O + o)       = make_float2(acc[mt][nt][0], acc[mt][nt][1]);
                *(float2*)(out + (size_t)(m + 8) * O + o) = make_float2(acc[mt][nt][2], acc[mt][nt][3]);
            }
        }
    }
}

// ---------------------------------------------------------------------------
extern "C" void kernel_launch(void* const* d_in, const int* in_sizes, int n_in,
                              void* d_out, int out_size)
{
    const float* x       = (const float*)d_in[0];
    const float* lora_A  = (const float*)d_in[1];
    const float* lora_B  = (const float*)d_in[2];
    const float* hidden0 = (const float*)d_in[3];
    const float* W_gate  = (const float*)d_in[4];
    const float* b_gate  = (const float*)d_in[5];
    const float* W_tau   = (const float*)d_in[6];
    const float* b_tau   = (const float*)d_in[7];
    float* out = (float*)d_out;

    int R = in_sizes[5];                 // 64
    int D = in_sizes[1] / R;             // 4096
    int O = in_sizes[2] / R;             // 4096
    int M = in_sizes[0] / D;             // 16384

    const int smemA = 35840;                   // max(2*16K stages, liquid WT2) + pad
    const int smemB = 3 * 16384 + 1024;        // 50176

    cudaFuncSetAttribute(fusedA,
                         cudaFuncAttributeMaxDynamicSharedMemorySize, smemA);
    cudaFuncSetAttribute(gemm2_mma,
                         cudaFuncAttributeMaxDynamicSharedMemorySize, smemB);

    int nA4 = (R * D) / 4;
    convA_kernel<<<(nA4 + 255) / 256, 256>>>(lora_A, nA4);

    int nG1 = M / 64;                    // 256
    fusedA<<<nG1 + NLIQ, 256, smemA>>>(x, lora_B, hidden0,
                                       W_gate, b_gate, W_tau, b_tau,
                                       M, D, O, nG1);

    dim3 g2(M / 128, O / 512);
    gemm2_mma<<<g2, 256, smemB>>>(out, M, O);
}

// round 12
// speedup vs baseline: 1.2650x; 1.0774x over previous
#include <cuda_runtime.h>
#include <cuda_fp16.h>
#include <math.h>
#include <stdint.h>

#define RR 64
#define DT_C 0.1f
#define TAU_MIN_C 0.1f
#define TAU_MAX_C 10.0f
#define SCALING_C 2.0f          // 128/64

#define MAX_M 16384
#define MAX_O 4096
#define MAX_D 4096

// scratch (device globals: no allocation allowed)
__device__ __align__(16) __half g_t[MAX_M * RR];      // 2 MB fp16 t
__device__ __align__(16) __half g_hB[MAX_O * RR];     // fp16 of 2*hidden
__device__ __align__(16) __half g_Ah[RR * MAX_D];     // fp16 of lora_A

// ---------------------------------------------------------------------------
// helpers
// ---------------------------------------------------------------------------
__device__ __forceinline__ uint32_t smem_u32(const void* p) {
    uint32_t a;
    asm("{ .reg .u64 t; cvta.to.shared.u64 t, %1; cvt.u32.u64 %0, t; }"
        : "=r"(a) : "l"(p));
    return a;
}
__device__ __forceinline__ uint32_t sw128(uint32_t o) { return o ^ ((o >> 3) & 0x70); }

__device__ __forceinline__ void sts128(uint32_t a, uint32_t x, uint32_t y,
                                       uint32_t z, uint32_t w) {
    asm volatile("st.shared.v4.b32 [%0], {%1,%2,%3,%4};"
                 :: "r"(a), "r"(x), "r"(y), "r"(z), "r"(w) : "memory");
}
__device__ __forceinline__ void ldm_x4(uint32_t* r, uint32_t addr) {
    asm volatile("ldmatrix.sync.aligned.m8n8.x4.shared.b16 {%0,%1,%2,%3}, [%4];"
                 : "=r"(r[0]), "=r"(r[1]), "=r"(r[2]), "=r"(r[3]) : "r"(addr));
}
__device__ __forceinline__ void cp16(uint32_t smem_dst, const void* gsrc) {
    asm volatile("cp.async.cg.shared.global [%0], [%1], 16;"
                 :: "r"(smem_dst), "l"(gsrc) : "memory");
}
#define CP_COMMIT() asm volatile("cp.async.commit_group;" ::: "memory")
#define CP_WAIT1()  asm volatile("cp.async.wait_group 1;" ::: "memory")

// D += A * B, fp16 inputs, fp32 accum
__device__ __forceinline__ void mma16816(float* d, const uint32_t* a, const uint32_t* b) {
    asm volatile(
        "mma.sync.aligned.m16n8k16.row.col.f32.f16.f16.f32 "
        "{%0,%1,%2,%3}, {%4,%5,%6,%7}, {%8,%9}, {%0,%1,%2,%3};"
        : "+f"(d[0]), "+f"(d[1]), "+f"(d[2]), "+f"(d[3])
        : "r"(a[0]), "r"(a[1]), "r"(a[2]), "r"(a[3]), "r"(b[0]), "r"(b[1]));
}
__device__ __forceinline__ uint32_t packH(float a, float b) {
    __half2 h = __floats2half2_rn(a, b);
    return *reinterpret_cast<uint32_t*>(&h);
}

// ---------------------------------------------------------------------------
// Kernel 0: convert lora_A (fp32) -> g_Ah (fp16). Tiny; runs first.
// ---------------------------------------------------------------------------
__global__ __launch_bounds__(256) void convA_kernel(const float* __restrict__ A, int n4)
{
    int i = blockIdx.x * 256 + threadIdx.x;
    if (i < n4) {
        float4 v = ((const float4*)A)[i];
        uint2 w;
        w.x = packH(v.x, v.y);
        w.y = packH(v.z, v.w);
        ((uint2*)g_Ah)[i] = w;
    }
}

// ---------------------------------------------------------------------------
// Fused kernel A:
//   blocks [0, nG1)      : GEMM1 t = x @ A^T, cp.async 3-stage ring.
//       x staged as RAW FP32 (row stride 72 floats, conflict-free LDS.64),
//       converted to fp16 fragments in the consumer (no ldmatrix for x).
//       A staged fp16 + SW128, consumed via ldmatrix.
//   blocks [nG1, nG1+32) : liquid dynamics (overlapped)
// ---------------------------------------------------------------------------
#define XSTRIDE 72                       // floats per x smem row (288 B)
#define X_BYTES (64 * XSTRIDE * 4)       // 18432
#define A_BYTES 8192
#define STAGE_BYTES (X_BYTES + A_BYTES)  // 26624
#define NSTAGE 3
#define NLIQ 32

__global__ __launch_bounds__(256, 2) void fusedA(
    const float* __restrict__ x,
    const float* __restrict__ lora_B, const float* __restrict__ hidden0,
    const float* __restrict__ W_gate, const float* __restrict__ b_gate,
    const float* __restrict__ W_tau,  const float* __restrict__ b_tau,
    int M, int D, int O, int nG1)
{
    extern __shared__ char dsm[];
    uint32_t sa  = smem_u32(dsm);
    uint32_t pad = (1024u - (sa & 1023u)) & 1023u;
    char*    bp  = dsm + pad;            // generic pointer, 1024-aligned
    uint32_t sb  = sa + pad;             // shared-space address, 1024-aligned
    int tid = threadIdx.x, wid = tid >> 5, lane = tid & 31;

    if ((int)blockIdx.x < nG1) {
        // ================= GEMM1: 64(M) x 64(N), K-tiles 64, cp.async ring ===
        int warp_m = wid >> 1, warp_n = wid & 1;
        int tt = lane >> 3, rr = lane & 7;
        int g4 = lane >> 2, tq = lane & 3;
        int tc = tq * 2;

        int m0 = blockIdx.x * 64;

        // x staging: 1024 16B-chunks/stage, 4 per thread
        int xrow[4], xc16[4];
        #pragma unroll
        for (int j = 0; j < 4; j++) {
            int c = tid + 256 * j;
            xrow[j] = c >> 4;  xc16[j] = c & 15;
        }
        // A staging: 512 chunks/stage, 2 per thread
        int arw[2], ac16[2];
        #pragma unroll
        for (int j = 0; j < 2; j++) {
            int c = tid + 256 * j;
            arw[j] = c >> 3;  ac16[j] = c & 7;
        }

        int b_row  = warp_n * 32 + (tt >> 1) * 8 + rr;
        int b_colb = (tt & 1) * 16;

        float acc[4][4];
        #pragma unroll
        for (int j = 0; j < 4; j++)
            #pragma unroll
            for (int k = 0; k < 4; k++) acc[j][k] = 0.0f;

        int nkt = D >> 6;

        // issue one stage of cp.async
        auto issue = [&](int kt, int slot) {
            uint32_t st = sb + slot * STAGE_BYTES;
            #pragma unroll
            for (int j = 0; j < 4; j++)
                cp16(st + xrow[j] * (XSTRIDE * 4) + xc16[j] * 16,
                     x + (size_t)(m0 + xrow[j]) * D + kt * 64 + xc16[j] * 4);
            uint32_t at = st + X_BYTES;
            #pragma unroll
            for (int j = 0; j < 2; j++)
                cp16(at + sw128((uint32_t)(arw[j] * 128 + ac16[j] * 16)),
                     g_Ah + (size_t)arw[j] * D + kt * 64 + ac16[j] * 8);
        };

        issue(0, 0); CP_COMMIT();
        issue(1, 1); CP_COMMIT();

        int fr = warp_m * 16 + g4;
        for (int kt = 0; kt < nkt; kt++) {
            int slot = kt % NSTAGE;
            CP_WAIT1();                   // stage kt arrived
            __syncthreads();              // all warps done with slot being refilled
            if (kt + 2 < nkt) issue(kt + 2, (kt + 2) % NSTAGE);
            CP_COMMIT();

            const float* xs = (const float*)(bp + slot * STAGE_BYTES);
            uint32_t     at = sb + slot * STAGE_BYTES + X_BYTES;

            #pragma unroll
            for (int kk = 0; kk < 4; kk++) {
                uint32_t bh[4][2];
                #pragma unroll
                for (int np = 0; np < 2; np++) {
                    uint32_t off = sw128((uint32_t)((b_row + np * 16) * 128 + b_colb + kk * 32));
                    uint32_t r4[4];
                    ldm_x4(r4, at + off);
                    bh[2*np][0] = r4[0]; bh[2*np][1] = r4[1];
                    bh[2*np+1][0] = r4[2]; bh[2*np+1][1] = r4[3];
                }
                // build x fragment from fp32 smem
                const float* p = xs + fr * XSTRIDE + tc + kk * 16;
                float2 v0 = *(const float2*)(p);
                float2 v1 = *(const float2*)(p + 8 * XSTRIDE);
                float2 v2 = *(const float2*)(p + 8);
                float2 v3 = *(const float2*)(p + 8 * XSTRIDE + 8);
                uint32_t ax[4];
                ax[0] = packH(v0.x, v0.y);
                ax[1] = packH(v1.x, v1.y);
                ax[2] = packH(v2.x, v2.y);
                ax[3] = packH(v3.x, v3.y);
                #pragma unroll
                for (int nt = 0; nt < 4; nt++)
                    mma16816(acc[nt], ax, bh[nt]);
            }
        }

        int m = m0 + warp_m * 16 + g4;
        #pragma unroll
        for (int nt = 0; nt < 4; nt++) {
            int n = warp_n * 32 + nt * 8 + 2 * tq;
            *(uint32_t*)(g_t + (size_t)m * RR + n)       = packH(acc[nt][0], acc[nt][1]);
            *(uint32_t*)(g_t + (size_t)(m + 8) * RR + n) = packH(acc[nt][2], acc[nt][3]);
        }
    } else {
        // ================= liquid path (unchanged) ===========================
        float* WT2 = (float*)(bp);           // [64][132] = 33792 B
        for (int idx = tid; idx < 128 * 64; idx += 256) {
            int r = idx >> 6, k2 = idx & 63;
            if (r < 64) WT2[k2 * 132 + r]             = W_gate[r * 128 + 64 + k2];
            else        WT2[k2 * 132 + 64 + (r - 64)] = W_tau[(r - 64) * 128 + 64 + k2];
        }
        __syncthreads();

        int lb = blockIdx.x - nG1;
        int gw = lb * 8 + wid;
        int rows_per_warp = O / (NLIQ * 8);          // 16
        int base = gw * rows_per_warp;

        float bg0 = b_gate[lane], bg1 = b_gate[lane + 32];
        float bt0 = b_tau[lane],  bt1 = b_tau[lane + 32];

        for (int p = 0; p < rows_per_warp / 4; p++) {
            int o4 = base + p * 4;
            float tg0[4], tg1[4], h0[4], h1[4];
            #pragma unroll
            for (int j = 0; j < 4; j++) {
                tg0[j] = lora_B[(size_t)(o4 + j) * RR + lane];
                tg1[j] = lora_B[(size_t)(o4 + j) * RR + lane + 32];
                h0[j]  = hidden0[(size_t)(o4 + j) * RR + lane];
                h1[j]  = hidden0[(size_t)(o4 + j) * RR + lane + 32];
            }

            float pg0[4], pg1[4], pt0[4], pt1[4];
            #pragma unroll
            for (int j = 0; j < 4; j++) { pg0[j] = bg0; pg1[j] = bg1; pt0[j] = bt0; pt1[j] = bt1; }
            #pragma unroll 2
            for (int k0 = 0; k0 < 32; k0 += 4) {
                float4 wg0A = *(const float4*)(W_gate + lane * 128 + k0);
                float4 wg1A = *(const float4*)(W_gate + (lane + 32) * 128 + k0);
                float4 wt0A = *(const float4*)(W_tau  + lane * 128 + k0);
                float4 wt1A = *(const float4*)(W_tau  + (lane + 32) * 128 + k0);
                float4 wg0B = *(const float4*)(W_gate + lane * 128 + 32 + k0);
                float4 wg1B = *(const float4*)(W_gate + (lane + 32) * 128 + 32 + k0);
                float4 wt0B = *(const float4*)(W_tau  + lane * 128 + 32 + k0);
                float4 wt1B = *(const float4*)(W_tau  + (lane + 32) * 128 + 32 + k0);
                #pragma unroll
                for (int e = 0; e < 4; e++) {
                    float g0 = ((const float*)&wg0A)[e], g1 = ((const float*)&wg1A)[e];
                    float t0 = ((const float*)&wt0A)[e], t1 = ((const float*)&wt1A)[e];
                    float g0b = ((const float*)&wg0B)[e], g1b = ((const float*)&wg1B)[e];
                    float t0b = ((const float*)&wt0B)[e], t1b = ((const float*)&wt1B)[e];
                    #pragma unroll
                    for (int j = 0; j < 4; j++) {
                        float v  = __shfl_sync(0xffffffffu, tg0[j], k0 + e);
                        float v2 = __shfl_sync(0xffffffffu, tg1[j], k0 + e);
                        pg0[j] += v * g0;   pg1[j] += v * g1;
                        pt0[j] += v * t0;   pt1[j] += v * t1;
                        pg0[j] += v2 * g0b; pg1[j] += v2 * g1b;
                        pt0[j] += v2 * t0b; pt1[j] += v2 * t1b;
                    }
                }
            }

            #pragma unroll
            for (int step = 0; step < 3; step++) {
                float ga0[4], ga1[4], ta0[4], ta1[4];
                #pragma unroll
                for (int j = 0; j < 4; j++) { ga0[j] = pg0[j]; ga1[j] = pg1[j]; ta0[j] = pt0[j]; ta1[j] = pt1[j]; }
                #pragma unroll 8
                for (int k = 0; k < 32; k++) {
                    float wg0 = WT2[k * 132 + lane],      wg1 = WT2[k * 132 + lane + 32];
                    float wt0 = WT2[k * 132 + 64 + lane], wt1 = WT2[k * 132 + 96 + lane];
                    float wg0b = WT2[(32 + k) * 132 + lane],      wg1b = WT2[(32 + k) * 132 + lane + 32];
                    float wt0b = WT2[(32 + k) * 132 + 64 + lane], wt1b = WT2[(32 + k) * 132 + 96 + lane];
                    #pragma unroll
                    for (int j = 0; j < 4; j++) {
                        float v  = __shfl_sync(0xffffffffu, h0[j], k);
                        float v2 = __shfl_sync(0xffffffffu, h1[j], k);
                        ga0[j] += v * wg0;  ga1[j] += v * wg1;
                        ta0[j] += v * wt0;  ta1[j] += v * wt1;
                        ga0[j] += v2 * wg0b; ga1[j] += v2 * wg1b;
                        ta0[j] += v2 * wt0b; ta1[j] += v2 * wt1b;
                    }
                }
                #pragma unroll
                for (int j = 0; j < 4; j++) {
                    float f0   = 1.0f / (1.0f + expf(-ga0[j]));
                    float f1   = 1.0f / (1.0f + expf(-ga1[j]));
                    float tau0 = TAU_MIN_C + (TAU_MAX_C - TAU_MIN_C) / (1.0f + expf(-ta0[j]));
                    float tau1 = TAU_MIN_C + (TAU_MAX_C - TAU_MIN_C) / (1.0f + expf(-ta1[j]));
                    float a0   = 1.0f / tau0 + f0;
                    float a1   = 1.0f / tau1 + f1;
                    float d0   = expf(-a0 * DT_C);
                    float d1   = expf(-a1 * DT_C);
                    h0[j] = h0[j] * d0 + (f0 / a0) * tg0[j] * (1.0f - d0);
                    h1[j] = h1[j] * d1 + (f1 / a1) * tg1[j] * (1.0f - d1);
                }
            }

            #pragma unroll
            for (int j = 0; j < 4; j++) {
                g_hB[(size_t)(o4 + j) * RR + lane]      = __float2half_rn(SCALING_C * h0[j]);
                g_hB[(size_t)(o4 + j) * RR + lane + 32] = __float2half_rn(SCALING_C * h1[j]);
            }
        }
    }
}

// ---------------------------------------------------------------------------
// Kernel B: out = t @ Bh^T (single-product fp16), K = 64 single shot.
// CTA: 128(M) x 512(O) via o-loop of 4 x 128-tiles; t in smem once,
// B double-buffered via register prefetch. 2 CTAs/SM. (unchanged from R11)
// ---------------------------------------------------------------------------
__global__ __launch_bounds__(256, 2) void gemm2_mma(
    float* __restrict__ out, int M, int O)
{
    extern __shared__ char dsm[];
    uint32_t sb  = (smem_u32(dsm) + 1023) & ~1023u;
    uint32_t thi = sb;                 // 16 KB
    uint32_t bst = sb + 16384;         // 2 x 16 KB B stages

    int tid = threadIdx.x, wid = tid >> 5, lane = tid & 31;
    int warp_m = wid & 1, warp_n = wid >> 1;
    int tt = lane >> 3, rr = lane & 7;
    int g  = lane >> 2, tq = lane & 3;

    int m0    = blockIdx.x * 128;
    int obase = blockIdx.y * 512;

    #pragma unroll
    for (int j = 0; j < 4; j++) {
        int i = tid + 256 * j;
        int row = i >> 3, c = i & 7;
        uint4 vh = ((const uint4*)(g_t + (size_t)(m0 + row) * RR))[c];
        sts128(thi + sw128((uint32_t)(row * 128 + c * 16)),
               vh.x, vh.y, vh.z, vh.w);
    }

    uint4 bv[4];
    #pragma unroll
    for (int j = 0; j < 4; j++) {
        int i = tid + 256 * j;
        int row = i >> 3, c = i & 7;
        bv[j] = ((const uint4*)(g_hB + (size_t)(obase + row) * RR))[c];
    }

    int a_row  = warp_m * 64 + (tt & 1) * 8 + rr;
    int a_colb = (tt >> 1) * 16;
    int b_row  = warp_n * 32 + (tt >> 1) * 8 + rr;
    int b_colb = (tt & 1) * 16;

    #pragma unroll 1
    for (int ot = 0; ot < 4; ot++) {
        int s = ot & 1;
        uint32_t bh_s = bst + s * 16384;
        int o0 = obase + ot * 128;

        #pragma unroll
        for (int j = 0; j < 4; j++) {
            int i = tid + 256 * j;
            int row = i >> 3, c = i & 7;
            sts128(bh_s + sw128((uint32_t)(row * 128 + c * 16)),
                   bv[j].x, bv[j].y, bv[j].z, bv[j].w);
        }
        __syncthreads();

        if (ot < 3) {
            #pragma unroll
            for (int j = 0; j < 4; j++) {
                int i = tid + 256 * j;
                int row = i >> 3, c = i & 7;
                bv[j] = ((const uint4*)(g_hB + (size_t)(obase + (ot + 1) * 128 + row) * RR))[c];
            }
        }

        float acc[4][4][4];
        #pragma unroll
        for (int i = 0; i < 4; i++)
            #pragma unroll
            for (int j = 0; j < 4; j++)
                #pragma unroll
                for (int k = 0; k < 4; k++) acc[i][j][k] = 0.0f;

        #pragma unroll
        for (int kk = 0; kk < 4; kk++) {
            uint32_t bh[4][2];
            #pragma unroll
            for (int np = 0; np < 2; np++) {
                uint32_t off = sw128((uint32_t)((b_row + np * 16) * 128 + b_colb + kk * 32));
                uint32_t r4[4];
                ldm_x4(r4, bh_s + off);
                bh[2*np][0] = r4[0]; bh[2*np][1] = r4[1];
                bh[2*np+1][0] = r4[2]; bh[2*np+1][1] = r4[3];
            }
            #pragma unroll
            for (int mt = 0; mt < 4; mt++) {
                uint32_t ath[4];
                uint32_t off = sw128((uint32_t)((a_row + mt * 16) * 128 + a_colb + kk * 32));
                ldm_x4(ath, thi + off);
                #pragma unroll
                for (int nt = 0; nt < 4; nt++)
                    mma16816(acc[mt][nt], ath, bh[nt]);
            }
        }

        #pragma unroll
        for (int mt = 0; mt < 4; mt++) {
            int m = m0 + warp_m * 64 + mt * 16 + g;
            #pragma unroll
            for (int nt = 0; nt < 4; nt++) {
                int o = o0 + warp_n * 32 + nt * 8 + 2 * tq;
                *(float2*)(out + (size_t)m * O + o)       = make_float2(acc[mt][nt][0], acc[mt][nt][1]);
                *(float2*)(out + (size_t)(m + 8) * O + o) = make_float2(acc[mt][nt][2], acc[mt][nt][3]);
            }
        }
    }
}

// ---------------------------------------------------------------------------
extern "C" void kernel_launch(void* const* d_in, const int* in_sizes, int n_in,
                              void* d_out, int out_size)
{
    const float* x       = (const float*)d_in[0];
    const float* lora_A  = (const float*)d_in[1];
    const float* lora_B  = (const float*)d_in[2];
    const float* hidden0 = (const float*)d_in[3];
    const float* W_gate  = (const float*)d_in[4];
    const float* b_gate  = (const float*)d_in[5];
    const float* W_tau   = (const float*)d_in[6];
    const float* b_tau   = (const float*)d_in[7];
    float* out = (float*)d_out;

    int R = in_sizes[5];                 // 64
    int D = in_sizes[1] / R;             // 4096
    int O = in_sizes[2] / R;             // 4096
    int M = in_sizes[0] / D;             // 16384

    const int smemA = NSTAGE * STAGE_BYTES + 1024;   // 80896
    const int smemB = 3 * 16384 + 1024;              // 50176

    cudaFuncSetAttribute(fusedA,
                         cudaFuncAttributeMaxDynamicSharedMemorySize, smemA);
    cudaFuncSetAttribute(gemm2_mma,
                         cudaFuncAttributeMaxDynamicSharedMemorySize, smemB);

    int nA4 = (R * D) / 4;
    convA_kernel<<<(nA4 + 255) / 256, 256>>>(lora_A, nA4);

    int nG1 = M / 64;                    // 256
    fusedA<<<nG1 + NLIQ, 256, smemA>>>(x, lora_B, hidden0,
                                       W_gate, b_gate, W_tau, b_tau,
                                       M, D, O, nG1);

    dim3 g2(M / 128, O / 512);
    gemm2_mma<<<g2, 256, smemB>>>(out, M, O);
}

// round 14
// speedup vs baseline: 1.3756x; 1.0874x over previous
#include <cuda_runtime.h>
#include <cuda_fp16.h>
#include <math.h>
#include <stdint.h>

#define RR 64
#define DT_C 0.1f
#define TAU_MIN_C 0.1f
#define TAU_MAX_C 10.0f
#define SCALING_C 2.0f          // 128/64

#define MAX_M 16384
#define MAX_O 4096
#define MAX_D 4096

// scratch (device globals: no allocation allowed)
__device__ __align__(16) __half g_t[MAX_M * RR];      // 2 MB fp16 t
__device__ __align__(16) __half g_hB[MAX_O * RR];     // fp16 of 2*hidden
__device__ __align__(16) __half g_Ah[RR * MAX_D];     // fp16 of lora_A

// ---------------------------------------------------------------------------
// helpers
// ---------------------------------------------------------------------------
__device__ __forceinline__ uint32_t smem_u32(const void* p) {
    uint32_t a;
    asm("{ .reg .u64 t; cvta.to.shared.u64 t, %1; cvt.u32.u64 %0, t; }"
        : "=r"(a) : "l"(p));
    return a;
}
__device__ __forceinline__ uint32_t sw128(uint32_t o) { return o ^ ((o >> 3) & 0x70); }

__device__ __forceinline__ void sts128(uint32_t a, uint32_t x, uint32_t y,
                                       uint32_t z, uint32_t w) {
    asm volatile("st.shared.v4.b32 [%0], {%1,%2,%3,%4};"
                 :: "r"(a), "r"(x), "r"(y), "r"(z), "r"(w) : "memory");
}
__device__ __forceinline__ void ldm_x4(uint32_t* r, uint32_t addr) {
    asm volatile("ldmatrix.sync.aligned.m8n8.x4.shared.b16 {%0,%1,%2,%3}, [%4];"
                 : "=r"(r[0]), "=r"(r[1]), "=r"(r[2]), "=r"(r[3]) : "r"(addr));
}
__device__ __forceinline__ void cp16(uint32_t smem_dst, const void* gsrc) {
    asm volatile("cp.async.cg.shared.global [%0], [%1], 16;"
                 :: "r"(smem_dst), "l"(gsrc) : "memory");
}
#define CP_COMMIT() asm volatile("cp.async.commit_group;" ::: "memory")
#define CP_WAIT1()  asm volatile("cp.async.wait_group 1;" ::: "memory")
#define CP_WAIT0()  asm volatile("cp.async.wait_group 0;" ::: "memory")

// D += A * B, fp16 inputs, fp32 accum
__device__ __forceinline__ void mma16816(float* d, const uint32_t* a, const uint32_t* b) {
    asm volatile(
        "mma.sync.aligned.m16n8k16.row.col.f32.f16.f16.f32 "
        "{%0,%1,%2,%3}, {%4,%5,%6,%7}, {%8,%9}, {%0,%1,%2,%3};"
        : "+f"(d[0]), "+f"(d[1]), "+f"(d[2]), "+f"(d[3])
        : "r"(a[0]), "r"(a[1]), "r"(a[2]), "r"(a[3]), "r"(b[0]), "r"(b[1]));
}
__device__ __forceinline__ uint32_t packH(float a, float b) {
    __half2 h = __floats2half2_rn(a, b);
    return *reinterpret_cast<uint32_t*>(&h);
}

// ---------------------------------------------------------------------------
// Kernel 0: convert lora_A (fp32) -> g_Ah (fp16). Tiny; runs first.
// ---------------------------------------------------------------------------
__global__ __launch_bounds__(256) void convA_kernel(const float* __restrict__ A, int n4)
{
    int i = blockIdx.x * 256 + threadIdx.x;
    if (i < n4) {
        float4 v = ((const float4*)A)[i];
        uint2 w;
        w.x = packH(v.x, v.y);
        w.y = packH(v.z, v.w);
        ((uint2*)g_Ah)[i] = w;
    }
}

// ---------------------------------------------------------------------------
// Fused kernel A (128 threads / 4 warps):
//   blocks [0, nG1)      : GEMM1 t = x @ A^T, cp.async 2-stage ring.
//       Warps 2(m) x 2(n), warp tile 32x32 — A-frag redundancy 2x.
//       x staged RAW FP32 (stride 72 floats, conflict-free LDS.64),
//       converted to fp16 fragments in the consumer. A staged fp16 + SW128.
//       4 CTAs/SM. COMMIT IS UNCONDITIONAL — wait_group 1 must always have
//       a trailing group to count, else the last K-tile is consumed early.
//   blocks [nG1, nG1+64) : liquid dynamics (overlapped)
// ---------------------------------------------------------------------------
#define XSTRIDE 72                       // floats per x smem row (288 B)
#define X_BYTES (64 * XSTRIDE * 4)       // 18432
#define A_BYTES 8192
#define STAGE_BYTES (X_BYTES + A_BYTES)  // 26624
#define NLIQ 64

__global__ __launch_bounds__(128, 4) void fusedA(
    const float* __restrict__ x,
    const float* __restrict__ lora_B, const float* __restrict__ hidden0,
    const float* __restrict__ W_gate, const float* __restrict__ b_gate,
    const float* __restrict__ W_tau,  const float* __restrict__ b_tau,
    int M, int D, int O, int nG1)
{
    extern __shared__ char dsm[];
    uint32_t sa  = smem_u32(dsm);
    uint32_t pad = (1024u - (sa & 1023u)) & 1023u;
    char*    bp  = dsm + pad;            // generic pointer, 1024-aligned
    uint32_t sb  = sa + pad;             // shared-space address, 1024-aligned
    int tid = threadIdx.x, wid = tid >> 5, lane = tid & 31;

    if ((int)blockIdx.x < nG1) {
        // ================= GEMM1: 64(M) x 64(N), K-tiles 64 ==================
        int warp_m = wid >> 1, warp_n = wid & 1;
        int tt = lane >> 3, rr = lane & 7;
        int g4 = lane >> 2, tq = lane & 3;
        int tc = tq * 2;

        int m0 = blockIdx.x * 64;

        int b_row  = warp_n * 32 + (tt >> 1) * 8 + rr;
        int b_colb = (tt & 1) * 16;

        float acc[2][4][4];
        #pragma unroll
        for (int i = 0; i < 2; i++)
            #pragma unroll
            for (int j = 0; j < 4; j++)
                #pragma unroll
                for (int k = 0; k < 4; k++) acc[i][j][k] = 0.0f;

        int nkt = D >> 6;

        // one stage of cp.async: x 1024 chunks (8/thr), A 512 chunks (4/thr)
        auto issue = [&](int kt, int slot) {
            uint32_t st = sb + slot * STAGE_BYTES;
            #pragma unroll
            for (int j = 0; j < 8; j++) {
                int c = tid + 128 * j;
                int row = c >> 4, c16 = c & 15;
                cp16(st + row * (XSTRIDE * 4) + c16 * 16,
                     x + (size_t)(m0 + row) * D + kt * 64 + c16 * 4);
            }
            uint32_t at = st + X_BYTES;
            #pragma unroll
            for (int j = 0; j < 4; j++) {
                int c = tid + 128 * j;
                int row = c >> 3, c16 = c & 7;
                cp16(at + sw128((uint32_t)(row * 128 + c16 * 16)),
                     g_Ah + (size_t)row * D + kt * 64 + c16 * 8);
            }
        };

        issue(0, 0); CP_COMMIT();
        issue(1, 1); CP_COMMIT();

        int fr = warp_m * 32 + g4;
        for (int kt = 0; kt < nkt; kt++) {
            int slot = kt & 1;
            CP_WAIT1();                   // stage kt arrived (this thread)
            __syncthreads();              // -> all threads' stage-kt chunks in

            const float* xs = (const float*)(bp + slot * STAGE_BYTES);
            uint32_t     at = sb + slot * STAGE_BYTES + X_BYTES;

            #pragma unroll
            for (int kk = 0; kk < 4; kk++) {
                uint32_t bh[4][2];
                #pragma unroll
                for (int np = 0; np < 2; np++) {
                    uint32_t off = sw128((uint32_t)((b_row + np * 16) * 128 + b_colb + kk * 32));
                    uint32_t r4[4];
                    ldm_x4(r4, at + off);
                    bh[2*np][0] = r4[0]; bh[2*np][1] = r4[1];
                    bh[2*np+1][0] = r4[2]; bh[2*np+1][1] = r4[3];
                }
                uint32_t ax[2][4];
                #pragma unroll
                for (int mt = 0; mt < 2; mt++) {
                    const float* p = xs + (fr + mt * 16) * XSTRIDE + tc + kk * 16;
                    float2 v0 = *(const float2*)(p);
                    float2 v1 = *(const float2*)(p + 8 * XSTRIDE);
                    float2 v2 = *(const float2*)(p + 8);
                    float2 v3 = *(const float2*)(p + 8 * XSTRIDE + 8);
                    ax[mt][0] = packH(v0.x, v0.y);
                    ax[mt][1] = packH(v1.x, v1.y);
                    ax[mt][2] = packH(v2.x, v2.y);
                    ax[mt][3] = packH(v3.x, v3.y);
                }
                #pragma unroll
                for (int mt = 0; mt < 2; mt++)
                    #pragma unroll
                    for (int nt = 0; nt < 4; nt++)
                        mma16816(acc[mt][nt], ax[mt], bh[nt]);
            }

            __syncthreads();              // everyone done reading slot
            if (kt + 2 < nkt)             // refill slot for tile kt+2
                issue(kt + 2, slot);
            CP_COMMIT();                  // UNCONDITIONAL (empty group on tail
                                          // keeps WAIT1 counting correct)
        }

        #pragma unroll
        for (int mt = 0; mt < 2; mt++) {
            int m = m0 + warp_m * 32 + mt * 16 + g4;
            #pragma unroll
            for (int nt = 0; nt < 4; nt++) {
                int n = warp_n * 32 + nt * 8 + 2 * tq;
                *(uint32_t*)(g_t + (size_t)m * RR + n)       = packH(acc[mt][nt][0], acc[mt][nt][1]);
                *(uint32_t*)(g_t + (size_t)(m + 8) * RR + n) = packH(acc[mt][nt][2], acc[mt][nt][3]);
            }
        }
    } else {
        // ================= liquid path (4 warps per block) ===================
        float* WT2 = (float*)(bp);           // [64][132] = 33792 B
        for (int idx = tid; idx < 128 * 64; idx += 128) {
            int r = idx >> 6, k2 = idx & 63;
            if (r < 64) WT2[k2 * 132 + r]             = W_gate[r * 128 + 64 + k2];
            else        WT2[k2 * 132 + 64 + (r - 64)] = W_tau[(r - 64) * 128 + 64 + k2];
        }
        __syncthreads();

        int lb = blockIdx.x - nG1;                   // 0..NLIQ-1
        int gw = lb * 4 + wid;                       // 0..255
        int rows_per_warp = O / (NLIQ * 4);          // 16
        int base = gw * rows_per_warp;

        float bg0 = b_gate[lane], bg1 = b_gate[lane + 32];
        float bt0 = b_tau[lane],  bt1 = b_tau[lane + 32];

        for (int p = 0; p < rows_per_warp / 4; p++) {
            int o4 = base + p * 4;
            float tg0[4], tg1[4], h0[4], h1[4];
            #pragma unroll
            for (int j = 0; j < 4; j++) {
                tg0[j] = lora_B[(size_t)(o4 + j) * RR + lane];
                tg1[j] = lora_B[(size_t)(o4 + j) * RR + lane + 32];
                h0[j]  = hidden0[(size_t)(o4 + j) * RR + lane];
                h1[j]  = hidden0[(size_t)(o4 + j) * RR + lane + 32];
            }

            float pg0[4], pg1[4], pt0[4], pt1[4];
            #pragma unroll
            for (int j = 0; j < 4; j++) { pg0[j] = bg0; pg1[j] = bg1; pt0[j] = bt0; pt1[j] = bt1; }
            #pragma unroll 2
            for (int k0 = 0; k0 < 32; k0 += 4) {
                float4 wg0A = *(const float4*)(W_gate + lane * 128 + k0);
                float4 wg1A = *(const float4*)(W_gate + (lane + 32) * 128 + k0);
                float4 wt0A = *(const float4*)(W_tau  + lane * 128 + k0);
                float4 wt1A = *(const float4*)(W_tau  + (lane + 32) * 128 + k0);
                float4 wg0B = *(const float4*)(W_gate + lane * 128 + 32 + k0);
                float4 wg1B = *(const float4*)(W_gate + (lane + 32) * 128 + 32 + k0);
                float4 wt0B = *(const float4*)(W_tau  + lane * 128 + 32 + k0);
                float4 wt1B = *(const float4*)(W_tau  + (lane + 32) * 128 + 32 + k0);
                #pragma unroll
                for (int e = 0; e < 4; e++) {
                    float g0 = ((const float*)&wg0A)[e], g1 = ((const float*)&wg1A)[e];
                    float t0 = ((const float*)&wt0A)[e], t1 = ((const float*)&wt1A)[e];
                    float g0b = ((const float*)&wg0B)[e], g1b = ((const float*)&wg1B)[e];
                    float t0b = ((const float*)&wt0B)[e], t1b = ((const float*)&wt1B)[e];
                    #pragma unroll
                    for (int j = 0; j < 4; j++) {
                        float v  = __shfl_sync(0xffffffffu, tg0[j], k0 + e);
                        float v2 = __shfl_sync(0xffffffffu, tg1[j], k0 + e);
                        pg0[j] += v * g0;   pg1[j] += v * g1;
                        pt0[j] += v * t0;   pt1[j] += v * t1;
                        pg0[j] += v2 * g0b; pg1[j] += v2 * g1b;
                        pt0[j] += v2 * t0b; pt1[j] += v2 * t1b;
                    }
                }
            }

            #pragma unroll
            for (int step = 0; step < 3; step++) {
                float ga0[4], ga1[4], ta0[4], ta1[4];
                #pragma unroll
                for (int j = 0; j < 4; j++) { ga0[j] = pg0[j]; ga1[j] = pg1[j]; ta0[j] = pt0[j]; ta1[j] = pt1[j]; }
                #pragma unroll 8
                for (int k = 0; k < 32; k++) {
                    float wg0 = WT2[k * 132 + lane],      wg1 = WT2[k * 132 + lane + 32];
                    float wt0 = WT2[k * 132 + 64 + lane], wt1 = WT2[k * 132 + 96 + lane];
                    float wg0b = WT2[(32 + k) * 132 + lane],      wg1b = WT2[(32 + k) * 132 + lane + 32];
                    float wt0b = WT2[(32 + k) * 132 + 64 + lane], wt1b = WT2[(32 + k) * 132 + 96 + lane];
                    #pragma unroll
                    for (int j = 0; j < 4; j++) {
                        float v  = __shfl_sync(0xffffffffu, h0[j], k);
                        float v2 = __shfl_sync(0xffffffffu, h1[j], k);
                        ga0[j] += v * wg0;  ga1[j] += v * wg1;
                        ta0[j] += v * wt0;  ta1[j] += v * wt1;
                        ga0[j] += v2 * wg0b; ga1[j] += v2 * wg1b;
                        ta0[j] += v2 * wt0b; ta1[j] += v2 * wt1b;
                    }
                }
                #pragma unroll
                for (int j = 0; j < 4; j++) {
                    float f0   = 1.0f / (1.0f + expf(-ga0[j]));
                    float f1   = 1.0f / (1.0f + expf(-ga1[j]));
                    float tau0 = TAU_MIN_C + (TAU_MAX_C - TAU_MIN_C) / (1.0f + expf(-ta0[j]));
                    float tau1 = TAU_MIN_C + (TAU_MAX_C - TAU_MIN_C) / (1.0f + expf(-ta1[j]));
                    float a0   = 1.0f / tau0 + f0;
                    float a1   = 1.0f / tau1 + f1;
                    float d0   = expf(-a0 * DT_C);
                    float d1   = expf(-a1 * DT_C);
                    h0[j] = h0[j] * d0 + (f0 / a0) * tg0[j] * (1.0f - d0);
                    h1[j] = h1[j] * d1 + (f1 / a1) * tg1[j] * (1.0f - d1);
                }
            }

            #pragma unroll
            for (int j = 0; j < 4; j++) {
                g_hB[(size_t)(o4 + j) * RR + lane]      = __float2half_rn(SCALING_C * h0[j]);
                g_hB[(size_t)(o4 + j) * RR + lane + 32] = __float2half_rn(SCALING_C * h1[j]);
            }
        }
    }
}

// ---------------------------------------------------------------------------
// Kernel B: out = t @ Bh^T (single-product fp16), K = 64 single shot.
// CTA: 128(M) x 512(O) via o-loop of 4 x 128-tiles; t in smem once,
// B staged via cp.async 2-stage ring (wait_group 0 -> conditional commit OK).
// 2 CTAs/SM.
// ---------------------------------------------------------------------------
__global__ __launch_bounds__(256, 2) void gemm2_mma(
    float* __restrict__ out, int M, int O)
{
    extern __shared__ char dsm[];
    uint32_t sb  = (smem_u32(dsm) + 1023) & ~1023u;
    uint32_t thi = sb;                 // 16 KB
    uint32_t bst = sb + 16384;         // 2 x 16 KB B stages

    int tid = threadIdx.x, wid = tid >> 5, lane = tid & 31;
    int warp_m = wid & 1, warp_n = wid >> 1;
    int tt = lane >> 3, rr = lane & 7;
    int g  = lane >> 2, tq = lane & 3;

    int m0    = blockIdx.x * 128;
    int obase = blockIdx.y * 512;

    // issue B tile via cp.async into stage (ot & 1)
    auto issueB = [&](int ot) {
        uint32_t bd = bst + (ot & 1) * 16384;
        #pragma unroll
        for (int j = 0; j < 4; j++) {
            int i = tid + 256 * j;
            int row = i >> 3, c = i & 7;
            cp16(bd + sw128((uint32_t)(row * 128 + c * 16)),
                 g_hB + (size_t)(obase + ot * 128 + row) * RR + c * 8);
        }
    };

    issueB(0); CP_COMMIT();

    // t tile into smem (once)
    #pragma unroll
    for (int j = 0; j < 4; j++) {
        int i = tid + 256 * j;
        int row = i >> 3, c = i & 7;
        uint4 vh = ((const uint4*)(g_t + (size_t)(m0 + row) * RR))[c];
        sts128(thi + sw128((uint32_t)(row * 128 + c * 16)),
               vh.x, vh.y, vh.z, vh.w);
    }

    int a_row  = warp_m * 64 + (tt & 1) * 8 + rr;
    int a_colb = (tt >> 1) * 16;
    int b_row  = warp_n * 32 + (tt >> 1) * 8 + rr;
    int b_colb = (tt & 1) * 16;

    #pragma unroll 1
    for (int ot = 0; ot < 4; ot++) {
        uint32_t bh_s = bst + (ot & 1) * 16384;
        int o0 = obase + ot * 128;

        CP_WAIT0();                       // ALL pending landed (B(ot))
        __syncthreads();                  // + prior reads of other stage done
        if (ot < 3) { issueB(ot + 1); CP_COMMIT(); }   // overlaps compute

        float acc[4][4][4];
        #pragma unroll
        for (int i = 0; i < 4; i++)
            #pragma unroll
            for (int j = 0; j < 4; j++)
                #pragma unroll
                for (int k = 0; k < 4; k++) acc[i][j][k] = 0.0f;

        #pragma unroll
        for (int kk = 0; kk < 4; kk++) {
            uint32_t bh[4][2];
            #pragma unroll
            for (int np = 0; np < 2; np++) {
                uint32_t off = sw128((uint32_t)((b_row + np * 16) * 128 + b_colb + kk * 32));
                uint32_t r4[4];
                ldm_x4(r4, bh_s + off);
                bh[2*np][0] = r4[0]; bh[2*np][1] = r4[1];
                bh[2*np+1][0] = r4[2]; bh[2*np+1][1] = r4[3];
            }
            #pragma unroll
            for (int mt = 0; mt < 4; mt++) {
                uint32_t ath[4];
                uint32_t off = sw128((uint32_t)((a_row + mt * 16) * 128 + a_colb + kk * 32));
                ldm_x4(ath, thi + off);
                #pragma unroll
                for (int nt = 0; nt < 4; nt++)
                    mma16816(acc[mt][nt], ath, bh[nt]);
            }
        }

        #pragma unroll
        for (int mt = 0; mt < 4; mt++) {
            int m = m0 + warp_m * 64 + mt * 16 + g;
            #pragma unroll
            for (int nt = 0; nt < 4; nt++) {
                int o = o0 + warp_n * 32 + nt * 8 + 2 * tq;
                *(float2*)(out + (size_t)m * O + o)       = make_float2(acc[mt][nt][0], acc[mt][nt][1]);
                *(float2*)(out + (size_t)(m + 8) * O + o) = make_float2(acc[mt][nt][2], acc[mt][nt][3]);
            }
        }
        __syncthreads();                  // all reads of bh_s done before refill
    }
}

// ---------------------------------------------------------------------------
extern "C" void kernel_launch(void* const* d_in, const int* in_sizes, int n_in,
                              void* d_out, int out_size)
{
    const float* x       = (const float*)d_in[0];
    const float* lora_A  = (const float*)d_in[1];
    const float* lora_B  = (const float*)d_in[2];
    const float* hidden0 = (const float*)d_in[3];
    const float* W_gate  = (const float*)d_in[4];
    const float* b_gate  = (const float*)d_in[5];
    const float* W_tau   = (const float*)d_in[6];
    const float* b_tau   = (const float*)d_in[7];
    float* out = (float*)d_out;

    int R = in_sizes[5];                 // 64
    int D = in_sizes[1] / R;             // 4096
    int O = in_sizes[2] / R;             // 4096
    int M = in_sizes[0] / D;             // 16384

    const int smemA = 2 * STAGE_BYTES + 1024;        // 54272 (covers liquid 34816)
    const int smemB = 3 * 16384 + 1024;              // 50176

    cudaFuncSetAttribute(fusedA,
                         cudaFuncAttributeMaxDynamicSharedMemorySize, smemA);
    cudaFuncSetAttribute(gemm2_mma,
                         cudaFuncAttributeMaxDynamicSharedMemorySize, smemB);

    int nA4 = (R * D) / 4;
    convA_kernel<<<(nA4 + 255) / 256, 256>>>(lora_A, nA4);

    int nG1 = M / 64;                    // 256
    fusedA<<<nG1 + NLIQ, 128, smemA>>>(x, lora_B, hidden0,
                                       W_gate, b_gate, W_tau, b_tau,
                                       M, D, O, nG1);

    dim3 g2(M / 128, O / 512);
    gemm2_mma<<<g2, 256, smemB>>>(out, M, O);
}

// round 15
// speedup vs baseline: 1.4573x; 1.0594x over previous
#include <cuda_runtime.h>
#include <cuda_fp16.h>
#include <math.h>
#include <stdint.h>

#define RR 64
#define DT_C 0.1f
#define TAU_MIN_C 0.1f
#define TAU_MAX_C 10.0f
#define SCALING_C 2.0f          // 128/64

#define MAX_M 16384
#define MAX_O 4096
#define MAX_D 4096

// scratch (device globals: no allocation allowed)
__device__ __align__(16) __half g_t[MAX_M * RR];      // 2 MB fp16 t
__device__ __align__(16) __half g_hB[MAX_O * RR];     // fp16 of 2*hidden
__device__ __align__(16) __half g_At[RR * MAX_D];     // A fp16, tiled+preswizzled:
                                                      // [kt][8192B], byte sw128(r*128+c*2)

// ---------------------------------------------------------------------------
// helpers
// ---------------------------------------------------------------------------
__device__ __forceinline__ uint32_t smem_u32(const void* p) {
    uint32_t a;
    asm("{ .reg .u64 t; cvta.to.shared.u64 t, %1; cvt.u32.u64 %0, t; }"
        : "=r"(a) : "l"(p));
    return a;
}
__device__ __forceinline__ uint32_t sw128(uint32_t o) { return o ^ ((o >> 3) & 0x70); }

__device__ __forceinline__ void sts128(uint32_t a, uint32_t x, uint32_t y,
                                       uint32_t z, uint32_t w) {
    asm volatile("st.shared.v4.b32 [%0], {%1,%2,%3,%4};"
                 :: "r"(a), "r"(x), "r"(y), "r"(z), "r"(w) : "memory");
}
__device__ __forceinline__ void ldm_x4(uint32_t* r, uint32_t addr) {
    asm volatile("ldmatrix.sync.aligned.m8n8.x4.shared.b16 {%0,%1,%2,%3}, [%4];"
                 : "=r"(r[0]), "=r"(r[1]), "=r"(r[2]), "=r"(r[3]) : "r"(addr));
}
__device__ __forceinline__ void cp16(uint32_t smem_dst, const void* gsrc) {
    asm volatile("cp.async.cg.shared.global [%0], [%1], 16;"
                 :: "r"(smem_dst), "l"(gsrc) : "memory");
}
#define CP_COMMIT() asm volatile("cp.async.commit_group;" ::: "memory")
#define CP_WAIT0()  asm volatile("cp.async.wait_group 0;" ::: "memory")

// 1D bulk copy gmem->smem, completes on mbarrier (UBLKCP.S.G)
__device__ __forceinline__ void cp_bulk(uint32_t smem_dst, const void* gsrc,
                                        uint32_t bytes, uint32_t mbar) {
    asm volatile(
        "cp.async.bulk.shared::cluster.global.mbarrier::complete_tx::bytes "
        "[%0], [%1], %2, [%3];"
        :: "r"(smem_dst), "l"(gsrc), "r"(bytes), "r"(mbar) : "memory");
}
#define MBAR_INIT(mbar, cnt) \
    asm volatile("mbarrier.init.shared.b64 [%0], %1;" :: "r"(mbar), "r"((uint32_t)(cnt)) : "memory")
#define MBAR_EXPECT_TX(mbar, bytes) \
    asm volatile("mbarrier.arrive.expect_tx.shared.b64 _, [%0], %1;" \
                 :: "r"(mbar), "r"((uint32_t)(bytes)) : "memory")
#define MBAR_WAIT(mbar, parity) do { \
    asm volatile("{\n\t.reg .pred P1;\n\t" \
        "WAIT_%=:\n\t" \
        "mbarrier.try_wait.parity.acquire.cta.shared::cta.b64 P1, [%0], %1, 0x989680;\n\t" \
        "@P1 bra.uni DONE_%=;\n\t" \
        "bra.uni WAIT_%=;\n\t" \
        "DONE_%=:\n\t}" \
        :: "r"(mbar), "r"((uint32_t)(parity)) : "memory"); \
} while (0)

// D += A * B, fp16 inputs, fp32 accum
__device__ __forceinline__ void mma16816(float* d, const uint32_t* a, const uint32_t* b) {
    asm volatile(
        "mma.sync.aligned.m16n8k16.row.col.f32.f16.f16.f32 "
        "{%0,%1,%2,%3}, {%4,%5,%6,%7}, {%8,%9}, {%0,%1,%2,%3};"
        : "+f"(d[0]), "+f"(d[1]), "+f"(d[2]), "+f"(d[3])
        : "r"(a[0]), "r"(a[1]), "r"(a[2]), "r"(a[3]), "r"(b[0]), "r"(b[1]));
}
__device__ __forceinline__ uint32_t packH(float a, float b) {
    __half2 h = __floats2half2_rn(a, b);
    return *reinterpret_cast<uint32_t*>(&h);
}

// ---------------------------------------------------------------------------
// Kernel 0: repack lora_A fp32 -> g_At fp16, per-K-tile contiguous 8KB blocks
// with SW128 swizzle pre-applied. i -> (r, kch): r=row 0..63, kch=8-float chunk.
// ---------------------------------------------------------------------------
__global__ __launch_bounds__(256) void convA_kernel(const float* __restrict__ A, int D)
{
    int i = blockIdx.x * 256 + threadIdx.x;          // 0 .. 64*(D/8)-1
    int ncol = D >> 3;
    if (i < 64 * ncol) {
        int r = i / ncol, kch = i % ncol;
        int kt = kch >> 3, c16 = kch & 7;
        const float4* s = (const float4*)(A + (size_t)r * D + kch * 8);
        float4 v0 = s[0], v1 = s[1];
        uint4 w;
        w.x = packH(v0.x, v0.y);
        w.y = packH(v0.z, v0.w);
        w.z = packH(v1.x, v1.y);
        w.w = packH(v1.z, v1.w);
        *(uint4*)((char*)g_At + kt * 8192 + sw128((uint32_t)(r * 128 + c16 * 16))) = w;
    }
}

// ---------------------------------------------------------------------------
// Fused kernel A (128 threads / 4 warps):
//   blocks [0, nG1)      : GEMM1 t = x @ A^T, BULK-staged 2-stage ring.
//       Per stage: 64 x-row bulks (256B, issued by 4 warp leaders) + one
//       8KB A bulk; completion via mbarrier expect_tx. Consumer identical
//       to R14 (fp32 x frags built via LDS.64+packH; A via ldmatrix).
//   blocks [nG1, nG1+64) : liquid dynamics (overlapped)
// ---------------------------------------------------------------------------
#define XSTRIDE 72                       // floats per x smem row (288 B)
#define X_BYTES (64 * XSTRIDE * 4)       // 18432
#define A_BYTES 8192
#define STAGE_BYTES (X_BYTES + A_BYTES)  // 26624
#define STAGE_TX    (64 * 256 + A_BYTES) // 24576 expected tx bytes
#define NLIQ 64

__global__ __launch_bounds__(128, 4) void fusedA(
    const float* __restrict__ x,
    const float* __restrict__ lora_B, const float* __restrict__ hidden0,
    const float* __restrict__ W_gate, const float* __restrict__ b_gate,
    const float* __restrict__ W_tau,  const float* __restrict__ b_tau,
    int M, int D, int O, int nG1)
{
    extern __shared__ char dsm[];
    __shared__ __align__(8) uint64_t s_mbar[2];
    uint32_t sa  = smem_u32(dsm);
    uint32_t pad = (1024u - (sa & 1023u)) & 1023u;
    char*    bp  = dsm + pad;            // generic pointer, 1024-aligned
    uint32_t sb  = sa + pad;             // shared-space address, 1024-aligned
    int tid = threadIdx.x, wid = tid >> 5, lane = tid & 31;

    if ((int)blockIdx.x < nG1) {
        // ================= GEMM1: 64(M) x 64(N), K-tiles 64 ==================
        int warp_m = wid >> 1, warp_n = wid & 1;
        int tt = lane >> 3, rr = lane & 7;
        int g4 = lane >> 2, tq = lane & 3;
        int tc = tq * 2;

        int m0 = blockIdx.x * 64;
        uint32_t mb0 = smem_u32(&s_mbar[0]);
        uint32_t mb1 = smem_u32(&s_mbar[1]);

        int b_row  = warp_n * 32 + (tt >> 1) * 8 + rr;
        int b_colb = (tt & 1) * 16;

        float acc[2][4][4];
        #pragma unroll
        for (int i = 0; i < 2; i++)
            #pragma unroll
            for (int j = 0; j < 4; j++)
                #pragma unroll
                for (int k = 0; k < 4; k++) acc[i][j][k] = 0.0f;

        int nkt = D >> 6;

        if (tid == 0) { MBAR_INIT(mb0, 1); MBAR_INIT(mb1, 1); }
        __syncthreads();

        // stage issue: warp leaders only. wid0 also expects tx + A bulk.
        auto issue = [&](int kt, int slot, uint32_t mbar) {
            if (lane == 0) {
                uint32_t st = sb + slot * STAGE_BYTES;
                if (wid == 0) {
                    MBAR_EXPECT_TX(mbar, STAGE_TX);
                    cp_bulk(st + X_BYTES, (const char*)g_At + (size_t)kt * 8192,
                            A_BYTES, mbar);
                }
                int r0 = wid * 16;
                #pragma unroll
                for (int r = 0; r < 16; r++)
                    cp_bulk(st + (r0 + r) * (XSTRIDE * 4),
                            x + (size_t)(m0 + r0 + r) * D + kt * 64,
                            256, mbar);
            }
        };

        issue(0, 0, mb0);
        issue(1, 1, mb1);

        int fr = warp_m * 32 + g4;
        for (int kt = 0; kt < nkt; kt++) {
            int slot = kt & 1;
            uint32_t mbar = slot ? mb1 : mb0;
            MBAR_WAIT(mbar, (kt >> 1) & 1);   // stage kt data visible (acquire)

            const float* xs = (const float*)(bp + slot * STAGE_BYTES);
            uint32_t     at = sb + slot * STAGE_BYTES + X_BYTES;

            #pragma unroll
            for (int kk = 0; kk < 4; kk++) {
                uint32_t bh[4][2];
                #pragma unroll
                for (int np = 0; np < 2; np++) {
                    uint32_t off = sw128((uint32_t)((b_row + np * 16) * 128 + b_colb + kk * 32));
                    uint32_t r4[4];
                    ldm_x4(r4, at + off);
                    bh[2*np][0] = r4[0]; bh[2*np][1] = r4[1];
                    bh[2*np+1][0] = r4[2]; bh[2*np+1][1] = r4[3];
                }
                uint32_t ax[2][4];
                #pragma unroll
                for (int mt = 0; mt < 2; mt++) {
                    const float* p = xs + (fr + mt * 16) * XSTRIDE + tc + kk * 16;
                    float2 v0 = *(const float2*)(p);
                    float2 v1 = *(const float2*)(p + 8 * XSTRIDE);
                    float2 v2 = *(const float2*)(p + 8);
                    float2 v3 = *(const float2*)(p + 8 * XSTRIDE + 8);
                    ax[mt][0] = packH(v0.x, v0.y);
                    ax[mt][1] = packH(v1.x, v1.y);
                    ax[mt][2] = packH(v2.x, v2.y);
                    ax[mt][3] = packH(v3.x, v3.y);
                }
                #pragma unroll
                for (int mt = 0; mt < 2; mt++)
                    #pragma unroll
                    for (int nt = 0; nt < 4; nt++)
                        mma16816(acc[mt][nt], ax[mt], bh[nt]);
            }

            __syncthreads();              // all warps done reading slot
            if (kt + 2 < nkt)
                issue(kt + 2, slot, mbar);
        }

        #pragma unroll
        for (int mt = 0; mt < 2; mt++) {
            int m = m0 + warp_m * 32 + mt * 16 + g4;
            #pragma unroll
            for (int nt = 0; nt < 4; nt++) {
                int n = warp_n * 32 + nt * 8 + 2 * tq;
                *(uint32_t*)(g_t + (size_t)m * RR + n)       = packH(acc[mt][nt][0], acc[mt][nt][1]);
                *(uint32_t*)(g_t + (size_t)(m + 8) * RR + n) = packH(acc[mt][nt][2], acc[mt][nt][3]);
            }
        }
    } else {
        // ================= liquid path (4 warps per block) ===================
        float* WT2 = (float*)(bp);           // [64][132] = 33792 B
        for (int idx = tid; idx < 128 * 64; idx += 128) {
            int r = idx >> 6, k2 = idx & 63;
            if (r < 64) WT2[k2 * 132 + r]             = W_gate[r * 128 + 64 + k2];
            else        WT2[k2 * 132 + 64 + (r - 64)] = W_tau[(r - 64) * 128 + 64 + k2];
        }
        __syncthreads();

        int lb = blockIdx.x - nG1;                   // 0..NLIQ-1
        int gw = lb * 4 + wid;                       // 0..255
        int rows_per_warp = O / (NLIQ * 4);          // 16
        int base = gw * rows_per_warp;

        float bg0 = b_gate[lane], bg1 = b_gate[lane + 32];
        float bt0 = b_tau[lane],  bt1 = b_tau[lane + 32];

        for (int p = 0; p < rows_per_warp / 4; p++) {
            int o4 = base + p * 4;
            float tg0[4], tg1[4], h0[4], h1[4];
            #pragma unroll
            for (int j = 0; j < 4; j++) {
                tg0[j] = lora_B[(size_t)(o4 + j) * RR + lane];
                tg1[j] = lora_B[(size_t)(o4 + j) * RR + lane + 32];
                h0[j]  = hidden0[(size_t)(o4 + j) * RR + lane];
                h1[j]  = hidden0[(size_t)(o4 + j) * RR + lane + 32];
            }

            float pg0[4], pg1[4], pt0[4], pt1[4];
            #pragma unroll
            for (int j = 0; j < 4; j++) { pg0[j] = bg0; pg1[j] = bg1; pt0[j] = bt0; pt1[j] = bt1; }
            #pragma unroll 2
            for (int k0 = 0; k0 < 32; k0 += 4) {
                float4 wg0A = *(const float4*)(W_gate + lane * 128 + k0);
                float4 wg1A = *(const float4*)(W_gate + (lane + 32) * 128 + k0);
                float4 wt0A = *(const float4*)(W_tau  + lane * 128 + k0);
                float4 wt1A = *(const float4*)(W_tau  + (lane + 32) * 128 + k0);
                float4 wg0B = *(const float4*)(W_gate + lane * 128 + 32 + k0);
                float4 wg1B = *(const float4*)(W_gate + (lane + 32) * 128 + 32 + k0);
                float4 wt0B = *(const float4*)(W_tau  + lane * 128 + 32 + k0);
                float4 wt1B = *(const float4*)(W_tau  + (lane + 32) * 128 + 32 + k0);
                #pragma unroll
                for (int e = 0; e < 4; e++) {
                    float g0 = ((const float*)&wg0A)[e], g1 = ((const float*)&wg1A)[e];
                    float t0 = ((const float*)&wt0A)[e], t1 = ((const float*)&wt1A)[e];
                    float g0b = ((const float*)&wg0B)[e], g1b = ((const float*)&wg1B)[e];
                    float t0b = ((const float*)&wt0B)[e], t1b = ((const float*)&wt1B)[e];
                    #pragma unroll
                    for (int j = 0; j < 4; j++) {
                        float v  = __shfl_sync(0xffffffffu, tg0[j], k0 + e);
                        float v2 = __shfl_sync(0xffffffffu, tg1[j], k0 + e);
                        pg0[j] += v * g0;   pg1[j] += v * g1;
                        pt0[j] += v * t0;   pt1[j] += v * t1;
                        pg0[j] += v2 * g0b; pg1[j] += v2 * g1b;
                        pt0[j] += v2 * t0b; pt1[j] += v2 * t1b;
                    }
                }
            }

            #pragma unroll
            for (int step = 0; step < 3; step++) {
                float ga0[4], ga1[4], ta0[4], ta1[4];
                #pragma unroll
                for (int j = 0; j < 4; j++) { ga0[j] = pg0[j]; ga1[j] = pg1[j]; ta0[j] = pt0[j]; ta1[j] = pt1[j]; }
                #pragma unroll 8
                for (int k = 0; k < 32; k++) {
                    float wg0 = WT2[k * 132 + lane],      wg1 = WT2[k * 132 + lane + 32];
                    float wt0 = WT2[k * 132 + 64 + lane], wt1 = WT2[k * 132 + 96 + lane];
                    float wg0b = WT2[(32 + k) * 132 + lane],      wg1b = WT2[(32 + k) * 132 + lane + 32];
                    float wt0b = WT2[(32 + k) * 132 + 64 + lane], wt1b = WT2[(32 + k) * 132 + 96 + lane];
                    #pragma unroll
                    for (int j = 0; j < 4; j++) {
                        float v  = __shfl_sync(0xffffffffu, h0[j], k);
                        float v2 = __shfl_sync(0xffffffffu, h1[j], k);
                        ga0[j] += v * wg0;  ga1[j] += v * wg1;
                        ta0[j] += v * wt0;  ta1[j] += v * wt1;
                        ga0[j] += v2 * wg0b; ga1[j] += v2 * wg1b;
                        ta0[j] += v2 * wt0b; ta1[j] += v2 * wt1b;
                    }
                }
                #pragma unroll
                for (int j = 0; j < 4; j++) {
                    float f0   = 1.0f / (1.0f + expf(-ga0[j]));
                    float f1   = 1.0f / (1.0f + expf(-ga1[j]));
                    float tau0 = TAU_MIN_C + (TAU_MAX_C - TAU_MIN_C) / (1.0f + expf(-ta0[j]));
                    float tau1 = TAU_MIN_C + (TAU_MAX_C - TAU_MIN_C) / (1.0f + expf(-ta1[j]));
                    float a0   = 1.0f / tau0 + f0;
                    float a1   = 1.0f / tau1 + f1;
                    float d0   = expf(-a0 * DT_C);
                    float d1   = expf(-a1 * DT_C);
                    h0[j] = h0[j] * d0 + (f0 / a0) * tg0[j] * (1.0f - d0);
                    h1[j] = h1[j] * d1 + (f1 / a1) * tg1[j] * (1.0f - d1);
                }
            }

            #pragma unroll
            for (int j = 0; j < 4; j++) {
                g_hB[(size_t)(o4 + j) * RR + lane]      = __float2half_rn(SCALING_C * h0[j]);
                g_hB[(size_t)(o4 + j) * RR + lane + 32] = __float2half_rn(SCALING_C * h1[j]);
            }
        }
    }
}

// ---------------------------------------------------------------------------
// Kernel B: out = t @ Bh^T (single-product fp16), K = 64 single shot.
// CTA: 128(M) x 512(O) via o-loop of 4 x 128-tiles; t in smem once,
// B staged via cp.async 2-stage ring. 2 CTAs/SM. (unchanged from R14)
// ---------------------------------------------------------------------------
__global__ __launch_bounds__(256, 2) void gemm2_mma(
    float* __restrict__ out, int M, int O)
{
    extern __shared__ char dsm[];
    uint32_t sb  = (smem_u32(dsm) + 1023) & ~1023u;
    uint32_t thi = sb;                 // 16 KB
    uint32_t bst = sb + 16384;         // 2 x 16 KB B stages

    int tid = threadIdx.x, wid = tid >> 5, lane = tid & 31;
    int warp_m = wid & 1, warp_n = wid >> 1;
    int tt = lane >> 3, rr = lane & 7;
    int g  = lane >> 2, tq = lane & 3;

    int m0    = blockIdx.x * 128;
    int obase = blockIdx.y * 512;

    auto issueB = [&](int ot) {
        uint32_t bd = bst + (ot & 1) * 16384;
        #pragma unroll
        for (int j = 0; j < 4; j++) {
            int i = tid + 256 * j;
            int row = i >> 3, c = i & 7;
            cp16(bd + sw128((uint32_t)(row * 128 + c * 16)),
                 g_hB + (size_t)(obase + ot * 128 + row) * RR + c * 8);
        }
    };

    issueB(0); CP_COMMIT();

    #pragma unroll
    for (int j = 0; j < 4; j++) {
        int i = tid + 256 * j;
        int row = i >> 3, c = i & 7;
        uint4 vh = ((const uint4*)(g_t + (size_t)(m0 + row) * RR))[c];
        sts128(thi + sw128((uint32_t)(row * 128 + c * 16)),
               vh.x, vh.y, vh.z, vh.w);
    }

    int a_row  = warp_m * 64 + (tt & 1) * 8 + rr;
    int a_colb = (tt >> 1) * 16;
    int b_row  = warp_n * 32 + (tt >> 1) * 8 + rr;
    int b_colb = (tt & 1) * 16;

    #pragma unroll 1
    for (int ot = 0; ot < 4; ot++) {
        uint32_t bh_s = bst + (ot & 1) * 16384;
        int o0 = obase + ot * 128;

        CP_WAIT0();
        __syncthreads();
        if (ot < 3) { issueB(ot + 1); CP_COMMIT(); }

        float acc[4][4][4];
        #pragma unroll
        for (int i = 0; i < 4; i++)
            #pragma unroll
            for (int j = 0; j < 4; j++)
                #pragma unroll
                for (int k = 0; k < 4; k++) acc[i][j][k] = 0.0f;

        #pragma unroll
        for (int kk = 0; kk < 4; kk++) {
            uint32_t bh[4][2];
            #pragma unroll
            for (int np = 0; np < 2; np++) {
                uint32_t off = sw128((uint32_t)((b_row + np * 16) * 128 + b_colb + kk * 32));
                uint32_t r4[4];
                ldm_x4(r4, bh_s + off);
                bh[2*np][0] = r4[0]; bh[2*np][1] = r4[1];
                bh[2*np+1][0] = r4[2]; bh[2*np+1][1] = r4[3];
            }
            #pragma unroll
            for (int mt = 0; mt < 4; mt++) {
                uint32_t ath[4];
                uint32_t off = sw128((uint32_t)((a_row + mt * 16) * 128 + a_colb + kk * 32));
                ldm_x4(ath, thi + off);
                #pragma unroll
                for (int nt = 0; nt < 4; nt++)
                    mma16816(acc[mt][nt], ath, bh[nt]);
            }
        }

        #pragma unroll
        for (int mt = 0; mt < 4; mt++) {
            int m = m0 + warp_m * 64 + mt * 16 + g;
            #pragma unroll
            for (int nt = 0; nt < 4; nt++) {
                int o = o0 + warp_n * 32 + nt * 8 + 2 * tq;
                *(float2*)(out + (size_t)m * O + o)       = make_float2(acc[mt][nt][0], acc[mt][nt][1]);
                *(float2*)(out + (size_t)(m + 8) * O + o) = make_float2(acc[mt][nt][2], acc[mt][nt][3]);
            }
        }
        __syncthreads();
    }
}

// ---------------------------------------------------------------------------
extern "C" void kernel_launch(void* const* d_in, const int* in_sizes, int n_in,
                              void* d_out, int out_size)
{
    const float* x       = (const float*)d_in[0];
    const float* lora_A  = (const float*)d_in[1];
    const float* lora_B  = (const float*)d_in[2];
    const float* hidden0 = (const float*)d_in[3];
    const float* W_gate  = (const float*)d_in[4];
    const float* b_gate  = (const float*)d_in[5];
    const float* W_tau   = (const float*)d_in[6];
    const float* b_tau   = (const float*)d_in[7];
    float* out = (float*)d_out;

    int R = in_sizes[5];                 // 64
    int D = in_sizes[1] / R;             // 4096
    int O = in_sizes[2] / R;             // 4096
    int M = in_sizes[0] / D;             // 16384

    const int smemA = 2 * STAGE_BYTES + 1024;        // 54272 (covers liquid 34816)
    const int smemB = 3 * 16384 + 1024;              // 50176

    cudaFuncSetAttribute(fusedA,
                         cudaFuncAttributeMaxDynamicSharedMemorySize, smemA);
    cudaFuncSetAttribute(gemm2_mma,
                         cudaFuncAttributeMaxDynamicSharedMemorySize, smemB);

    int nChunk = 64 * (D / 8);           // 32768
    convA_kernel<<<(nChunk + 255) / 256, 256>>>(lora_A, D);

    int nG1 = M / 64;                    // 256
    fusedA<<<nG1 + NLIQ, 128, smemA>>>(x, lora_B, hidden0,
                                       W_gate, b_gate, W_tau, b_tau,
                                       M, D, O, nG1);

    dim3 g2(M / 128, O / 512);
    gemm2_mma<<<g2, 256, smemB>>>(out, M, O);
}